// round 1
// baseline (speedup 1.0000x reference)
#include <cuda_runtime.h>
#include <cuda_bf16.h>
#include <math.h>

// Problem shape (fixed by the dataset): B=8192, D=H=1024, 4H=4096
#define BB   8192
#define HH   1024
#define FH   4096
#define KK   1024
#define EPSL 1e-5f

// Scratch for the two gate pre-activation matrices: g1 = h0@Wh, g2 = x@Wx
// 2 * 8192 * 4096 floats = 268 MB, static device allocation (allowed).
__device__ float g_scratch[2ULL * BB * FH];

// ---------------------------------------------------------------------------
// GEMM: C = A[M,K] @ W[K,N], all row-major. M=8192, N=4096, K=1024.
// 128x128 block tile, BK=16, 8x8 per-thread micro-tile, 256 threads.
// ---------------------------------------------------------------------------
#define BM 128
#define BN 128
#define BK 16
#define TM 8
#define TN 8

__global__ void __launch_bounds__(256, 2)
sgemm_kernel(const float* __restrict__ A, const float* __restrict__ W, int which)
{
    const int M = BB, N = FH, K = KK;
    __shared__ float As[BK][BM];
    __shared__ float Bs[BK][BN];

    float* C = g_scratch + (size_t)which * (size_t)M * (size_t)N;

    const int m0  = blockIdx.y * BM;
    const int n0  = blockIdx.x * BN;
    const int tid = threadIdx.x;
    const int tx  = tid % (BN / TN);   // 0..15 (n direction)
    const int ty  = tid / (BN / TN);   // 0..15 (m direction)

    float acc[TM][TN];
#pragma unroll
    for (int i = 0; i < TM; i++)
#pragma unroll
        for (int j = 0; j < TN; j++) acc[i][j] = 0.f;

    for (int k0 = 0; k0 < K; k0 += BK) {
        // Load A tile (BM x BK = 2048 floats = 512 float4), transpose into As[k][m]
#pragma unroll
        for (int l = 0; l < 2; l++) {
            int idx = tid + l * 256;          // 0..511
            int r   = idx >> 2;               // 0..127  (row within tile)
            int cs  = (idx & 3) << 2;         // 0,4,8,12 (k segment)
            float4 v = *reinterpret_cast<const float4*>(
                &A[(size_t)(m0 + r) * K + k0 + cs]);
            As[cs + 0][r] = v.x;
            As[cs + 1][r] = v.y;
            As[cs + 2][r] = v.z;
            As[cs + 3][r] = v.w;
        }
        // Load B tile (BK x BN = 2048 floats = 512 float4), coalesced
#pragma unroll
        for (int l = 0; l < 2; l++) {
            int idx = tid + l * 256;
            int r   = idx >> 5;               // 0..15
            int c   = (idx & 31) << 2;        // 0..124
            *reinterpret_cast<float4*>(&Bs[r][c]) =
                *reinterpret_cast<const float4*>(
                    &W[(size_t)(k0 + r) * N + n0 + c]);
        }
        __syncthreads();

#pragma unroll
        for (int k = 0; k < BK; k++) {
            float ra[TM], rb[TN];
#pragma unroll
            for (int i = 0; i < TM; i += 4) {
                float4 v = *reinterpret_cast<const float4*>(&As[k][ty * TM + i]);
                ra[i] = v.x; ra[i + 1] = v.y; ra[i + 2] = v.z; ra[i + 3] = v.w;
            }
#pragma unroll
            for (int j = 0; j < TN; j += 4) {
                float4 v = *reinterpret_cast<const float4*>(&Bs[k][tx * TN + j]);
                rb[j] = v.x; rb[j + 1] = v.y; rb[j + 2] = v.z; rb[j + 3] = v.w;
            }
#pragma unroll
            for (int i = 0; i < TM; i++)
#pragma unroll
                for (int j = 0; j < TN; j++)
                    acc[i][j] = fmaf(ra[i], rb[j], acc[i][j]);
        }
        __syncthreads();
    }

#pragma unroll
    for (int i = 0; i < TM; i++) {
#pragma unroll
        for (int j = 0; j < TN; j += 4) {
            float4 v = make_float4(acc[i][j], acc[i][j + 1], acc[i][j + 2], acc[i][j + 3]);
            *reinterpret_cast<float4*>(
                &C[(size_t)(m0 + ty * TM + i) * N + n0 + tx * TN + j]) = v;
        }
    }
}

// ---------------------------------------------------------------------------
// Fused LSTM epilogue: per row b (8192 blocks, 512 threads):
//   gates = LN(g1) + LN(g2) + bias    (LN over 4096)
//   c1 = sig(f)*c0 + sig(i)*tanh(c)
//   h1 = sig(o)*tanh(LN(c1))          (LN over 1024)
//   out = [h1 ; c1]  (concatenated, each B*H floats)
// ---------------------------------------------------------------------------
__device__ __forceinline__ float sigf(float x) { return 1.f / (1.f + expf(-x)); }

__global__ void __launch_bounds__(512)
lstm_epilogue(const float* __restrict__ c0,   const float* __restrict__ bias,
              const float* __restrict__ ln1g, const float* __restrict__ ln1b,
              const float* __restrict__ ln2g, const float* __restrict__ ln2b,
              const float* __restrict__ ln3g, const float* __restrict__ ln3b,
              float* __restrict__ out)
{
    const int b = blockIdx.x;
    const int t = threadIdx.x;          // 0..511
    const int warp = t >> 5;
    const int lane = t & 31;

    const float* g1 = g_scratch + (size_t)b * FH;
    const float* g2 = g_scratch + (size_t)BB * FH + (size_t)b * FH;

    __shared__ float sm[16 * 4];

    // --- load gate pre-activations, accumulate sum / sumsq for LN1 & LN2 ---
    float v1[8], v2[8];
    float s0 = 0.f, s1 = 0.f, s2 = 0.f, s3 = 0.f;  // sum1, sq1, sum2, sq2
#pragma unroll
    for (int k = 0; k < 8; k++) {
        int j = t + k * 512;
        float a = g1[j], c = g2[j];
        v1[k] = a; v2[k] = c;
        s0 += a; s1 += a * a;
        s2 += c; s3 += c * c;
    }
#pragma unroll
    for (int o = 16; o > 0; o >>= 1) {
        s0 += __shfl_xor_sync(0xffffffffu, s0, o);
        s1 += __shfl_xor_sync(0xffffffffu, s1, o);
        s2 += __shfl_xor_sync(0xffffffffu, s2, o);
        s3 += __shfl_xor_sync(0xffffffffu, s3, o);
    }
    if (lane == 0) {
        sm[warp * 4 + 0] = s0; sm[warp * 4 + 1] = s1;
        sm[warp * 4 + 2] = s2; sm[warp * 4 + 3] = s3;
    }
    __syncthreads();
    float t0 = 0.f, t1 = 0.f, t2 = 0.f, t3 = 0.f;
#pragma unroll
    for (int w = 0; w < 16; w++) {
        t0 += sm[w * 4 + 0]; t1 += sm[w * 4 + 1];
        t2 += sm[w * 4 + 2]; t3 += sm[w * 4 + 3];
    }
    const float inv4h = 1.f / (float)FH;
    float mu1 = t0 * inv4h;
    float rs1 = rsqrtf(t1 * inv4h - mu1 * mu1 + EPSL);
    float mu2 = t2 * inv4h;
    float rs2 = rsqrtf(t3 * inv4h - mu2 * mu2 + EPSL);

    // --- LSTM cell math for this thread's 2 hidden indices ---
    // v1[k]/v2[k] holds gate column (t + k*512):
    //   k=0,1 -> forget [0,1024)   k=2,3 -> input [1024,2048)
    //   k=4,5 -> output [2048,3072) k=6,7 -> cell [3072,4096)
    float c1v[2], ogv[2];
    float u0 = 0.f, u1 = 0.f;   // sum / sumsq of c1 for LN3
#pragma unroll
    for (int p = 0; p < 2; p++) {
        int i = t + p * 512;
        int jf = i, ji = i + HH, jo = i + 2 * HH, jc = i + 3 * HH;
        float nf = (v1[p + 0] - mu1) * rs1 * ln1g[jf] + ln1b[jf]
                 + (v2[p + 0] - mu2) * rs2 * ln2g[jf] + ln2b[jf] + bias[jf];
        float ni = (v1[p + 2] - mu1) * rs1 * ln1g[ji] + ln1b[ji]
                 + (v2[p + 2] - mu2) * rs2 * ln2g[ji] + ln2b[ji] + bias[ji];
        float no = (v1[p + 4] - mu1) * rs1 * ln1g[jo] + ln1b[jo]
                 + (v2[p + 4] - mu2) * rs2 * ln2g[jo] + ln2b[jo] + bias[jo];
        float nc = (v1[p + 6] - mu1) * rs1 * ln1g[jc] + ln1b[jc]
                 + (v2[p + 6] - mu2) * rs2 * ln2g[jc] + ln2b[jc] + bias[jc];
        float c1 = sigf(nf) * c0[(size_t)b * HH + i] + sigf(ni) * tanhf(nc);
        c1v[p] = c1;
        ogv[p] = no;
        u0 += c1; u1 += c1 * c1;
    }

    // --- LN3 reduction over 1024 c1 values ---
    __syncthreads();   // everyone done reading sm from first reduction
#pragma unroll
    for (int o = 16; o > 0; o >>= 1) {
        u0 += __shfl_xor_sync(0xffffffffu, u0, o);
        u1 += __shfl_xor_sync(0xffffffffu, u1, o);
    }
    if (lane == 0) { sm[warp * 2 + 0] = u0; sm[warp * 2 + 1] = u1; }
    __syncthreads();
    float w0 = 0.f, w1 = 0.f;
#pragma unroll
    for (int w = 0; w < 16; w++) { w0 += sm[w * 2 + 0]; w1 += sm[w * 2 + 1]; }
    const float invh = 1.f / (float)HH;
    float mu3 = w0 * invh;
    float rs3 = rsqrtf(w1 * invh - mu3 * mu3 + EPSL);

#pragma unroll
    for (int p = 0; p < 2; p++) {
        int i = t + p * 512;
        float hn = (c1v[p] - mu3) * rs3 * ln3g[i] + ln3b[i];
        float h1 = sigf(ogv[p]) * tanhf(hn);
        out[(size_t)b * HH + i] = h1;                              // h1 block
        out[(size_t)BB * HH + (size_t)b * HH + i] = c1v[p];        // c1 block
    }
}

// ---------------------------------------------------------------------------
// Launch. Inputs (metadata order):
// 0:x 1:h0 2:c0 3:weight_h 4:weight_x 5:bias 6:ln1_g 7:ln1_b 8:ln2_g 9:ln2_b
// 10:ln3_g 11:ln3_b ; output: [h1 (B*H) ; c1 (B*H)] float32
// ---------------------------------------------------------------------------
extern "C" void kernel_launch(void* const* d_in, const int* in_sizes, int n_in,
                              void* d_out, int out_size)
{
    const float* x    = (const float*)d_in[0];
    const float* h0   = (const float*)d_in[1];
    const float* c0   = (const float*)d_in[2];
    const float* Wh   = (const float*)d_in[3];
    const float* Wx   = (const float*)d_in[4];
    const float* bias = (const float*)d_in[5];
    const float* ln1g = (const float*)d_in[6];
    const float* ln1b = (const float*)d_in[7];
    const float* ln2g = (const float*)d_in[8];
    const float* ln2b = (const float*)d_in[9];
    const float* ln3g = (const float*)d_in[10];
    const float* ln3b = (const float*)d_in[11];
    float* out = (float*)d_out;

    dim3 grid(FH / BN, BB / BM);   // (32, 64)
    sgemm_kernel<<<grid, 256>>>(h0, Wh, 0);   // g1 = h0 @ Wh
    sgemm_kernel<<<grid, 256>>>(x,  Wx, 1);   // g2 = x  @ Wx

    lstm_epilogue<<<BB, 512>>>(c0, bias, ln1g, ln1b, ln2g, ln2b, ln3g, ln3b, out);
}

// round 3
// speedup vs baseline: 1.9548x; 1.9548x over previous
#include <cuda_runtime.h>
#include <cuda_bf16.h>
#include <math.h>
#include <cstdint>

// Problem shape (fixed): B=8192, D=H=1024, 4H=4096
#define BB   8192
#define HH   1024
#define FH   4096
#define KK   1024
#define KEXT 3072          // [hi | hi | lo] concatenated K
#define EPSL 1e-5f

// ---------------------------------------------------------------------------
// Static device scratch
// ---------------------------------------------------------------------------
__device__ float g_scratch[2ULL * BB * FH];                    // g1, g2 fp32
__device__ __nv_bfloat16 g_aex[2][(size_t)BB * KEXT];          // A' (h0, x)
__device__ __nv_bfloat16 g_wex[2][(size_t)FH * KEXT];          // W'^T (Wh, Wx)

// ---------------------------------------------------------------------------
// Conversion: activations fp32 [BB,KK] -> A' bf16 [BB, 3072] = [hi|hi|lo]
// ---------------------------------------------------------------------------
__global__ void __launch_bounds__(256)
split_act(const float* __restrict__ in, int which)
{
    size_t i = (size_t)blockIdx.x * 256 + threadIdx.x;   // float4 index
    float4 v = reinterpret_cast<const float4*>(in)[i];
    float vv[4] = {v.x, v.y, v.z, v.w};
    union { __nv_bfloat16 b[4]; uint2 u; } Hh, Ll;
#pragma unroll
    for (int j = 0; j < 4; j++) {
        Hh.b[j] = __float2bfloat16_rn(vv[j]);
        Ll.b[j] = __float2bfloat16_rn(vv[j] - __bfloat162float(Hh.b[j]));
    }
    size_t row = i >> 8;                 // 256 float4 per row of 1024
    size_t col = (i & 255) * 4;
    __nv_bfloat16* base = g_aex[which] + row * KEXT + col;
    *reinterpret_cast<uint2*>(base)          = Hh.u;
    *reinterpret_cast<uint2*>(base + 1024)   = Hh.u;
    *reinterpret_cast<uint2*>(base + 2048)   = Ll.u;
}

// W [KK, FH] fp32 -> W'^T [FH, 3072] bf16 = [hi | lo | hi] along k
__global__ void __launch_bounds__(256)
split_wT(const float* __restrict__ W, int which)
{
    __shared__ float ts[32][33];
    int n0 = blockIdx.x * 32, k0 = blockIdx.y * 32;
    int tx = threadIdx.x & 31, ty = threadIdx.x >> 5;   // ty 0..7
#pragma unroll
    for (int d = 0; d < 32; d += 8)
        ts[ty + d][tx] = W[(size_t)(k0 + ty + d) * FH + n0 + tx];
    __syncthreads();
#pragma unroll
    for (int d = 0; d < 4; d++) {
        int nl = ty + d * 8;
        float v = ts[tx][nl];
        __nv_bfloat16 h = __float2bfloat16_rn(v);
        __nv_bfloat16 l = __float2bfloat16_rn(v - __bfloat162float(h));
        __nv_bfloat16* base = g_wex[which] + (size_t)(n0 + nl) * KEXT + k0 + tx;
        base[0]    = h;
        base[1024] = l;
        base[2048] = h;
    }
}

// ---------------------------------------------------------------------------
// HMMA GEMM: C[M,N] = A'[M,KEXT] @ W'^T[N,KEXT]^T
// CTA tile 128x256, BK=32, 256 threads (8 warps, 2x4 grid of 64x64 warp tiles)
// 3-stage cp.async pipeline. Smem rows padded to 80B (conflict-free ldmatrix).
// ---------------------------------------------------------------------------
#define BM 128
#define BN 256
#define BK 32
#define ROWB 80u                    // padded row stride in bytes (32 bf16 -> 80B)
#define AS_BYTES (BM * ROWB)        // 10240
#define BS_BYTES (BN * ROWB)        // 20480
#define STG_BYTES (AS_BYTES + BS_BYTES)   // 30720
#define NSTAGE 3
#define GEMM_SMEM (NSTAGE * STG_BYTES)    // 92160
#define ITERS (KEXT / BK)           // 96

__device__ __forceinline__ uint32_t smem_u32(const void* p) {
    uint32_t a;
    asm("{ .reg .u64 t; cvta.to.shared.u64 t, %1; cvt.u32.u64 %0, t; }"
        : "=r"(a) : "l"(p));
    return a;
}

__device__ __forceinline__ void ldmx4(uint32_t* r, uint32_t addr) {
    asm volatile("ldmatrix.sync.aligned.m8n8.x4.shared.b16 {%0,%1,%2,%3}, [%4];"
                 : "=r"(r[0]), "=r"(r[1]), "=r"(r[2]), "=r"(r[3]) : "r"(addr));
}

__device__ __forceinline__ void mma16816(float* d, const uint32_t* a,
                                         const uint32_t* b) {
    asm volatile(
        "mma.sync.aligned.m16n8k16.row.col.f32.bf16.bf16.f32 "
        "{%0,%1,%2,%3}, {%4,%5,%6,%7}, {%8,%9}, {%0,%1,%2,%3};"
        : "+f"(d[0]), "+f"(d[1]), "+f"(d[2]), "+f"(d[3])
        : "r"(a[0]), "r"(a[1]), "r"(a[2]), "r"(a[3]), "r"(b[0]), "r"(b[1]));
}

__device__ __forceinline__ void load_stage(const __nv_bfloat16* __restrict__ Aex,
                                           const __nv_bfloat16* __restrict__ Wex,
                                           int m0, int n0, int k0,
                                           uint32_t stage_base, int tid)
{
    // A tile: 128 rows x 32 k (4 chunks of 16B per row) = 512 chunks
#pragma unroll
    for (int j = 0; j < 2; j++) {
        int idx = tid + j * 256;
        int r = idx >> 2, c = idx & 3;
        const void* g = Aex + (size_t)(m0 + r) * KEXT + k0 + c * 8;
        uint32_t sa = stage_base + (uint32_t)r * ROWB + (uint32_t)c * 16;
        asm volatile("cp.async.cg.shared.global [%0], [%1], 16;" :: "r"(sa), "l"(g));
    }
    // B tile: 256 rows x 32 k = 1024 chunks
    uint32_t bs = stage_base + AS_BYTES;
#pragma unroll
    for (int j = 0; j < 4; j++) {
        int idx = tid + j * 256;
        int r = idx >> 2, c = idx & 3;
        const void* g = Wex + (size_t)(n0 + r) * KEXT + k0 + c * 8;
        uint32_t sa = bs + (uint32_t)r * ROWB + (uint32_t)c * 16;
        asm volatile("cp.async.cg.shared.global [%0], [%1], 16;" :: "r"(sa), "l"(g));
    }
}

__global__ void __launch_bounds__(256, 1)
hmma_gemm(int which)
{
    extern __shared__ char smem[];
    const uint32_t sb = smem_u32(smem);
    const int tid  = threadIdx.x;
    const int wid  = tid >> 5;
    const int lane = tid & 31;
    const int wm   = wid >> 2;            // 0..1
    const int wn   = wid & 3;             // 0..3
    const int n0   = blockIdx.x * BN;
    const int m0   = blockIdx.y * BM;

    const __nv_bfloat16* Aex = g_aex[which];
    const __nv_bfloat16* Wex = g_wex[which];
    float* C = g_scratch + (size_t)which * BB * FH;

    // per-lane ldmatrix byte offsets (relative to stage base), kh adds 32
    const int quad = lane >> 3, lrow = lane & 7;
    uint32_t a_off[4], b_off[4];
#pragma unroll
    for (int mi = 0; mi < 4; mi++) {
        int row = wm * 64 + mi * 16 + (quad & 1) * 8 + lrow;
        a_off[mi] = (uint32_t)row * ROWB + (uint32_t)(quad >> 1) * 16;
    }
#pragma unroll
    for (int np = 0; np < 4; np++) {
        int row = wn * 64 + np * 16 + (quad >> 1) * 8 + lrow;
        b_off[np] = AS_BYTES + (uint32_t)row * ROWB + (uint32_t)(quad & 1) * 16;
    }

    float d[4][8][4];
#pragma unroll
    for (int mi = 0; mi < 4; mi++)
#pragma unroll
        for (int nt = 0; nt < 8; nt++)
#pragma unroll
            for (int q = 0; q < 4; q++) d[mi][nt][q] = 0.f;

    // prologue: stages 0 and 1
    load_stage(Aex, Wex, m0, n0, 0, sb, tid);
    asm volatile("cp.async.commit_group;");
    load_stage(Aex, Wex, m0, n0, BK, sb + STG_BYTES, tid);
    asm volatile("cp.async.commit_group;");

    for (int it = 0; it < ITERS; it++) {
        asm volatile("cp.async.wait_group %0;" :: "n"(1) : "memory");
        __syncthreads();

        if (it + 2 < ITERS)
            load_stage(Aex, Wex, m0, n0, (it + 2) * BK,
                       sb + (uint32_t)((it + 2) % NSTAGE) * STG_BYTES, tid);
        asm volatile("cp.async.commit_group;");

        const uint32_t st = sb + (uint32_t)(it % NSTAGE) * STG_BYTES;
#pragma unroll
        for (int kh = 0; kh < 2; kh++) {
            uint32_t a[4][4], b[4][4];
#pragma unroll
            for (int mi = 0; mi < 4; mi++)
                ldmx4(a[mi], st + a_off[mi] + kh * 32);
#pragma unroll
            for (int np = 0; np < 4; np++)
                ldmx4(b[np], st + b_off[np] + kh * 32);
#pragma unroll
            for (int mi = 0; mi < 4; mi++)
#pragma unroll
                for (int np = 0; np < 4; np++) {
                    mma16816(d[mi][np * 2 + 0], a[mi], &b[np][0]);
                    mma16816(d[mi][np * 2 + 1], a[mi], &b[np][2]);
                }
        }
    }

    // epilogue: direct float2 stores (32B sector-aligned per 4-lane group)
    const int r_base = m0 + wm * 64 + (lane >> 2);
    const int c_base = n0 + wn * 64 + (lane & 3) * 2;
#pragma unroll
    for (int mi = 0; mi < 4; mi++) {
#pragma unroll
        for (int nt = 0; nt < 8; nt++) {
            int rr = r_base + mi * 16;
            int cc = c_base + nt * 8;
            *reinterpret_cast<float2*>(C + (size_t)rr * FH + cc) =
                make_float2(d[mi][nt][0], d[mi][nt][1]);
            *reinterpret_cast<float2*>(C + (size_t)(rr + 8) * FH + cc) =
                make_float2(d[mi][nt][2], d[mi][nt][3]);
        }
    }
}

// ---------------------------------------------------------------------------
// Fused LSTM epilogue (unchanged from passing baseline)
// ---------------------------------------------------------------------------
__device__ __forceinline__ float sigf(float x) { return 1.f / (1.f + expf(-x)); }

__global__ void __launch_bounds__(512)
lstm_epilogue(const float* __restrict__ c0,   const float* __restrict__ bias,
              const float* __restrict__ ln1g, const float* __restrict__ ln1b,
              const float* __restrict__ ln2g, const float* __restrict__ ln2b,
              const float* __restrict__ ln3g, const float* __restrict__ ln3b,
              float* __restrict__ out)
{
    const int b = blockIdx.x;
    const int t = threadIdx.x;
    const int warp = t >> 5;
    const int lane = t & 31;

    const float* g1 = g_scratch + (size_t)b * FH;
    const float* g2 = g_scratch + (size_t)BB * FH + (size_t)b * FH;

    __shared__ float sm[16 * 4];

    float v1[8], v2[8];
    float s0 = 0.f, s1 = 0.f, s2 = 0.f, s3 = 0.f;
#pragma unroll
    for (int k = 0; k < 8; k++) {
        int j = t + k * 512;
        float a = g1[j], c = g2[j];
        v1[k] = a; v2[k] = c;
        s0 += a; s1 += a * a;
        s2 += c; s3 += c * c;
    }
#pragma unroll
    for (int o = 16; o > 0; o >>= 1) {
        s0 += __shfl_xor_sync(0xffffffffu, s0, o);
        s1 += __shfl_xor_sync(0xffffffffu, s1, o);
        s2 += __shfl_xor_sync(0xffffffffu, s2, o);
        s3 += __shfl_xor_sync(0xffffffffu, s3, o);
    }
    if (lane == 0) {
        sm[warp * 4 + 0] = s0; sm[warp * 4 + 1] = s1;
        sm[warp * 4 + 2] = s2; sm[warp * 4 + 3] = s3;
    }
    __syncthreads();
    float t0 = 0.f, t1 = 0.f, t2 = 0.f, t3 = 0.f;
#pragma unroll
    for (int w = 0; w < 16; w++) {
        t0 += sm[w * 4 + 0]; t1 += sm[w * 4 + 1];
        t2 += sm[w * 4 + 2]; t3 += sm[w * 4 + 3];
    }
    const float inv4h = 1.f / (float)FH;
    float mu1 = t0 * inv4h;
    float rs1 = rsqrtf(t1 * inv4h - mu1 * mu1 + EPSL);
    float mu2 = t2 * inv4h;
    float rs2 = rsqrtf(t3 * inv4h - mu2 * mu2 + EPSL);

    float c1v[2], ogv[2];
    float u0 = 0.f, u1 = 0.f;
#pragma unroll
    for (int p = 0; p < 2; p++) {
        int i = t + p * 512;
        int jf = i, ji = i + HH, jo = i + 2 * HH, jc = i + 3 * HH;
        float nf = (v1[p + 0] - mu1) * rs1 * ln1g[jf] + ln1b[jf]
                 + (v2[p + 0] - mu2) * rs2 * ln2g[jf] + ln2b[jf] + bias[jf];
        float ni = (v1[p + 2] - mu1) * rs1 * ln1g[ji] + ln1b[ji]
                 + (v2[p + 2] - mu2) * rs2 * ln2g[ji] + ln2b[ji] + bias[ji];
        float no = (v1[p + 4] - mu1) * rs1 * ln1g[jo] + ln1b[jo]
                 + (v2[p + 4] - mu2) * rs2 * ln2g[jo] + ln2b[jo] + bias[jo];
        float nc = (v1[p + 6] - mu1) * rs1 * ln1g[jc] + ln1b[jc]
                 + (v2[p + 6] - mu2) * rs2 * ln2g[jc] + ln2b[jc] + bias[jc];
        float c1 = sigf(nf) * c0[(size_t)b * HH + i] + sigf(ni) * tanhf(nc);
        c1v[p] = c1;
        ogv[p] = no;
        u0 += c1; u1 += c1 * c1;
    }

    __syncthreads();
#pragma unroll
    for (int o = 16; o > 0; o >>= 1) {
        u0 += __shfl_xor_sync(0xffffffffu, u0, o);
        u1 += __shfl_xor_sync(0xffffffffu, u1, o);
    }
    if (lane == 0) { sm[warp * 2 + 0] = u0; sm[warp * 2 + 1] = u1; }
    __syncthreads();
    float w0 = 0.f, w1 = 0.f;
#pragma unroll
    for (int w = 0; w < 16; w++) { w0 += sm[w * 2 + 0]; w1 += sm[w * 2 + 1]; }
    const float invh = 1.f / (float)HH;
    float mu3 = w0 * invh;
    float rs3 = rsqrtf(w1 * invh - mu3 * mu3 + EPSL);

#pragma unroll
    for (int p = 0; p < 2; p++) {
        int i = t + p * 512;
        float hn = (c1v[p] - mu3) * rs3 * ln3g[i] + ln3b[i];
        float h1 = sigf(ogv[p]) * tanhf(hn);
        out[(size_t)b * HH + i] = h1;
        out[(size_t)BB * HH + (size_t)b * HH + i] = c1v[p];
    }
}

// ---------------------------------------------------------------------------
// Launch
// ---------------------------------------------------------------------------
extern "C" void kernel_launch(void* const* d_in, const int* in_sizes, int n_in,
                              void* d_out, int out_size)
{
    const float* x    = (const float*)d_in[0];
    const float* h0   = (const float*)d_in[1];
    const float* c0   = (const float*)d_in[2];
    const float* Wh   = (const float*)d_in[3];
    const float* Wx   = (const float*)d_in[4];
    const float* bias = (const float*)d_in[5];
    const float* ln1g = (const float*)d_in[6];
    const float* ln1b = (const float*)d_in[7];
    const float* ln2g = (const float*)d_in[8];
    const float* ln2b = (const float*)d_in[9];
    const float* ln3g = (const float*)d_in[10];
    const float* ln3b = (const float*)d_in[11];
    float* out = (float*)d_out;

    static bool attr_set = false;
    if (!attr_set) {
        cudaFuncSetAttribute(hmma_gemm,
                             cudaFuncAttributeMaxDynamicSharedMemorySize,
                             GEMM_SMEM);
        attr_set = true;
    }

    // split conversions
    split_act<<<BB * KK / 1024, 256>>>(h0, 0);
    split_act<<<BB * KK / 1024, 256>>>(x, 1);
    split_wT<<<dim3(FH / 32, KK / 32), 256>>>(Wh, 0);
    split_wT<<<dim3(FH / 32, KK / 32), 256>>>(Wx, 1);

    // tensor-core GEMMs (HMMA via mma.sync)
    dim3 ggrid(FH / BN, BB / BM);   // (16, 64)
    hmma_gemm<<<ggrid, 256, GEMM_SMEM>>>(0);   // g1 = h0 @ Wh
    hmma_gemm<<<ggrid, 256, GEMM_SMEM>>>(1);   // g2 = x  @ Wx

    lstm_epilogue<<<BB, 512>>>(c0, bias, ln1g, ln1b, ln2g, ln2b, ln3g, ln3b, out);
}

// round 4
// speedup vs baseline: 2.0166x; 1.0316x over previous
#include <cuda_runtime.h>
#include <cuda_bf16.h>
#include <math.h>
#include <cstdint>

// Problem shape (fixed): B=8192, D=H=1024, 4H=4096
#define BB   8192
#define HH   1024
#define FH   4096
#define KK   1024
#define EPSL 1e-5f

// ---------------------------------------------------------------------------
// Static device scratch
// g_ahi / g_whi : bf16 hi parts (K=1024), row stride 2048 B
// g_a8 : fp8 [ Ahi*4 | Alo*512 ]  (K=2048), row stride 2048 B
// g_w8 : fp8 [ Blo*4096 | Bhi*32 ] (K=2048), row stride 2048 B
// corr = Ahi*Blo*2^14 + Alo*Bhi*2^14  -> rescale accumulator by 2^-14
// ---------------------------------------------------------------------------
__device__ float g_scratch[2ULL * BB * FH];
__device__ __nv_bfloat16 g_ahi[2][(size_t)BB * KK];
__device__ __nv_bfloat16 g_whi[2][(size_t)FH * KK];
__device__ uint8_t g_a8[2][(size_t)BB * 2 * KK];
__device__ uint8_t g_w8[2][(size_t)FH * 2 * KK];

// ---------------------------------------------------------------------------
// helpers
// ---------------------------------------------------------------------------
__device__ __forceinline__ uint32_t smem_u32(const void* p) {
    uint32_t a;
    asm("{ .reg .u64 t; cvta.to.shared.u64 t, %1; cvt.u32.u64 %0, t; }"
        : "=r"(a) : "l"(p));
    return a;
}

// pack two floats -> two e4m3 bytes; e0 -> low byte (first in memory)
__device__ __forceinline__ uint16_t pack_e4m3(float e0, float e1) {
    uint16_t r;
    asm("cvt.rn.satfinite.e4m3x2.f32 %0, %1, %2;" : "=h"(r) : "f"(e1), "f"(e0));
    return r;
}

__device__ __forceinline__ void ldmx4(uint32_t* r, uint32_t addr) {
    asm volatile("ldmatrix.sync.aligned.m8n8.x4.shared.b16 {%0,%1,%2,%3}, [%4];"
                 : "=r"(r[0]), "=r"(r[1]), "=r"(r[2]), "=r"(r[3]) : "r"(addr));
}

__device__ __forceinline__ void mma_bf16(float* d, const uint32_t* a,
                                         const uint32_t* b) {
    asm volatile(
        "mma.sync.aligned.m16n8k16.row.col.f32.bf16.bf16.f32 "
        "{%0,%1,%2,%3}, {%4,%5,%6,%7}, {%8,%9}, {%0,%1,%2,%3};"
        : "+f"(d[0]), "+f"(d[1]), "+f"(d[2]), "+f"(d[3])
        : "r"(a[0]), "r"(a[1]), "r"(a[2]), "r"(a[3]), "r"(b[0]), "r"(b[1]));
}

__device__ __forceinline__ void mma_fp8(float* d, const uint32_t* a,
                                        const uint32_t* b) {
    asm volatile(
        "mma.sync.aligned.m16n8k32.row.col.f32.e4m3.e4m3.f32 "
        "{%0,%1,%2,%3}, {%4,%5,%6,%7}, {%8,%9}, {%0,%1,%2,%3};"
        : "+f"(d[0]), "+f"(d[1]), "+f"(d[2]), "+f"(d[3])
        : "r"(a[0]), "r"(a[1]), "r"(a[2]), "r"(a[3]), "r"(b[0]), "r"(b[1]));
}

// ---------------------------------------------------------------------------
// Conversions
// ---------------------------------------------------------------------------
__global__ void __launch_bounds__(256)
conv_act(const float* __restrict__ in, int which)
{
    size_t i = (size_t)blockIdx.x * 256 + threadIdx.x;   // float4 index
    float4 v = reinterpret_cast<const float4*>(in)[i];
    float vv[4] = {v.x, v.y, v.z, v.w};
    union { __nv_bfloat16 b[4]; uint2 u; } Hh;
    float hif[4], lof[4];
#pragma unroll
    for (int j = 0; j < 4; j++) {
        Hh.b[j] = __float2bfloat16_rn(vv[j]);
        hif[j]  = __bfloat162float(Hh.b[j]);
        lof[j]  = vv[j] - hif[j];
    }
    size_t row = i >> 8, col = (i & 255) * 4;
    *reinterpret_cast<uint2*>(g_ahi[which] + row * KK + col) = Hh.u;
    uint32_t hi8 = (uint32_t)pack_e4m3(4.f * hif[0], 4.f * hif[1])
                 | ((uint32_t)pack_e4m3(4.f * hif[2], 4.f * hif[3]) << 16);
    uint32_t lo8 = (uint32_t)pack_e4m3(512.f * lof[0], 512.f * lof[1])
                 | ((uint32_t)pack_e4m3(512.f * lof[2], 512.f * lof[3]) << 16);
    *reinterpret_cast<uint32_t*>(g_a8[which] + row * 2048 + col)        = hi8;
    *reinterpret_cast<uint32_t*>(g_a8[which] + row * 2048 + 1024 + col) = lo8;
}

// W [KK, FH] fp32 -> transposed hi bf16 + fp8 [Blo*4096 | Bhi*32]
__global__ void __launch_bounds__(256)
conv_w(const float* __restrict__ W, int which)
{
    __shared__ float ts[32][33];
    int n0 = blockIdx.x * 32, k0 = blockIdx.y * 32;
    int tx = threadIdx.x & 31, ty = threadIdx.x >> 5;   // ty 0..7
#pragma unroll
    for (int d = 0; d < 32; d += 8)
        ts[ty + d][tx] = W[(size_t)(k0 + ty + d) * FH + n0 + tx];
    __syncthreads();
#pragma unroll
    for (int d = 0; d < 4; d++) {
        int nl = ty + d * 8;
        float v = ts[tx][nl];
        __nv_bfloat16 h = __float2bfloat16_rn(v);
        float hf = __bfloat162float(h);
        float lf = v - hf;
        int n = n0 + nl, k = k0 + tx;
        g_whi[which][(size_t)n * KK + k] = h;
        uint16_t lo2 = pack_e4m3(4096.f * lf, 0.f);
        uint16_t hi2 = pack_e4m3(32.f * hf, 0.f);
        g_w8[which][(size_t)n * 2048 + k]        = (uint8_t)(lo2 & 0xFF);
        g_w8[which][(size_t)n * 2048 + 1024 + k] = (uint8_t)(hi2 & 0xFF);
    }
}

// ---------------------------------------------------------------------------
// GEMM: C[M,N] = corr*2^-14 + Ahi@Whi^T
// CTA tile 128x256, 256 threads, 64B of k-bytes per iter (3-stage cp.async).
// iters 0..31: fp8 correction (k32 fp8 per kh-half)
// iters 32..63: bf16 hi*hi    (k16 bf16 per kh-half)
// ---------------------------------------------------------------------------
#define BM 128
#define BN 256
#define ROWB 80u
#define AS_BYTES (BM * ROWB)
#define BS_BYTES (BN * ROWB)
#define STG_BYTES (AS_BYTES + BS_BYTES)    // 30720
#define NSTAGE 3
#define GEMM_SMEM (NSTAGE * STG_BYTES)     // 92160
#define GROWB 2048                          // global row stride (bytes), all buffers

__device__ __forceinline__ void load_stage(const char* __restrict__ Ab,
                                           const char* __restrict__ Bb,
                                           int kbyte, uint32_t stage_base, int tid)
{
#pragma unroll
    for (int j = 0; j < 2; j++) {
        int idx = tid + j * 256;
        int r = idx >> 2, c = idx & 3;
        const void* g = Ab + (size_t)r * GROWB + kbyte + c * 16;
        uint32_t sa = stage_base + (uint32_t)r * ROWB + (uint32_t)c * 16;
        asm volatile("cp.async.cg.shared.global [%0], [%1], 16;" :: "r"(sa), "l"(g));
    }
    uint32_t bs = stage_base + AS_BYTES;
#pragma unroll
    for (int j = 0; j < 4; j++) {
        int idx = tid + j * 256;
        int r = idx >> 2, c = idx & 3;
        const void* g = Bb + (size_t)r * GROWB + kbyte + c * 16;
        uint32_t sa = bs + (uint32_t)r * ROWB + (uint32_t)c * 16;
        asm volatile("cp.async.cg.shared.global [%0], [%1], 16;" :: "r"(sa), "l"(g));
    }
}

__global__ void __launch_bounds__(256, 1)
hmma_gemm()
{
    extern __shared__ char smem[];
    const uint32_t sb = smem_u32(smem);
    const int tid  = threadIdx.x;
    const int wid  = tid >> 5;
    const int lane = tid & 31;
    const int wm   = wid >> 2;            // 0..1
    const int wn   = wid & 3;             // 0..3
    const int n0   = blockIdx.x * BN;
    const int m0   = blockIdx.y * BM;
    const int which = blockIdx.z;

    const char* A8 = (const char*)g_a8[which] + (size_t)m0 * GROWB;
    const char* B8 = (const char*)g_w8[which] + (size_t)n0 * GROWB;
    const char* Ah = (const char*)g_ahi[which] + (size_t)m0 * GROWB;
    const char* Bh = (const char*)g_whi[which] + (size_t)n0 * GROWB;
    float* C = g_scratch + (size_t)which * BB * FH;

    // per-lane ldmatrix byte offsets (relative to stage base); kh adds 32
    const int quad = lane >> 3, lrow = lane & 7;
    uint32_t a_off[4], b_off[4];
#pragma unroll
    for (int mi = 0; mi < 4; mi++) {
        int row = wm * 64 + mi * 16 + (quad & 1) * 8 + lrow;
        a_off[mi] = (uint32_t)row * ROWB + (uint32_t)(quad >> 1) * 16;
    }
#pragma unroll
    for (int np = 0; np < 4; np++) {
        int row = wn * 64 + np * 16 + (quad >> 1) * 8 + lrow;
        b_off[np] = AS_BYTES + (uint32_t)row * ROWB + (uint32_t)(quad & 1) * 16;
    }

    float d[4][8][4];
#pragma unroll
    for (int mi = 0; mi < 4; mi++)
#pragma unroll
        for (int nt = 0; nt < 8; nt++)
#pragma unroll
            for (int q = 0; q < 4; q++) d[mi][nt][q] = 0.f;

    // prologue: stages 0 and 1 (both fp8 phase)
    load_stage(A8, B8, 0, sb, tid);
    asm volatile("cp.async.commit_group;");
    load_stage(A8, B8, 64, sb + STG_BYTES, tid);
    asm volatile("cp.async.commit_group;");

#pragma unroll 1
    for (int it = 0; it < 64; it++) {
        asm volatile("cp.async.wait_group %0;" :: "n"(1) : "memory");
        __syncthreads();

        int li = it + 2;
        if (li < 64) {
            const char* Ab = (li < 32) ? A8 : Ah;
            const char* Bb = (li < 32) ? B8 : Bh;
            load_stage(Ab, Bb, (li & 31) * 64,
                       sb + (uint32_t)(li % NSTAGE) * STG_BYTES, tid);
        }
        asm volatile("cp.async.commit_group;");

        if (it == 32) {
            const float s = 6.103515625e-05f;   // 2^-14
#pragma unroll
            for (int mi = 0; mi < 4; mi++)
#pragma unroll
                for (int nt = 0; nt < 8; nt++)
#pragma unroll
                    for (int q = 0; q < 4; q++) d[mi][nt][q] *= s;
        }

        const uint32_t st = sb + (uint32_t)(it % NSTAGE) * STG_BYTES;
#pragma unroll
        for (int kh = 0; kh < 2; kh++) {
            uint32_t a[4][4], b[4][4];
#pragma unroll
            for (int mi = 0; mi < 4; mi++)
                ldmx4(a[mi], st + a_off[mi] + kh * 32);
#pragma unroll
            for (int np = 0; np < 4; np++)
                ldmx4(b[np], st + b_off[np] + kh * 32);
            if (it < 32) {
#pragma unroll
                for (int mi = 0; mi < 4; mi++)
#pragma unroll
                    for (int np = 0; np < 4; np++) {
                        mma_fp8(d[mi][np * 2 + 0], a[mi], &b[np][0]);
                        mma_fp8(d[mi][np * 2 + 1], a[mi], &b[np][2]);
                    }
            } else {
#pragma unroll
                for (int mi = 0; mi < 4; mi++)
#pragma unroll
                    for (int np = 0; np < 4; np++) {
                        mma_bf16(d[mi][np * 2 + 0], a[mi], &b[np][0]);
                        mma_bf16(d[mi][np * 2 + 1], a[mi], &b[np][2]);
                    }
            }
        }
    }

    // epilogue: direct float2 stores
    const int r_base = m0 + wm * 64 + (lane >> 2);
    const int c_base = n0 + wn * 64 + (lane & 3) * 2;
#pragma unroll
    for (int mi = 0; mi < 4; mi++) {
#pragma unroll
        for (int nt = 0; nt < 8; nt++) {
            int rr = r_base + mi * 16;
            int cc = c_base + nt * 8;
            *reinterpret_cast<float2*>(C + (size_t)rr * FH + cc) =
                make_float2(d[mi][nt][0], d[mi][nt][1]);
            *reinterpret_cast<float2*>(C + (size_t)(rr + 8) * FH + cc) =
                make_float2(d[mi][nt][2], d[mi][nt][3]);
        }
    }
}

// ---------------------------------------------------------------------------
// Fused LSTM epilogue (unchanged)
// ---------------------------------------------------------------------------
__device__ __forceinline__ float sigf(float x) { return 1.f / (1.f + expf(-x)); }

__global__ void __launch_bounds__(512)
lstm_epilogue(const float* __restrict__ c0,   const float* __restrict__ bias,
              const float* __restrict__ ln1g, const float* __restrict__ ln1b,
              const float* __restrict__ ln2g, const float* __restrict__ ln2b,
              const float* __restrict__ ln3g, const float* __restrict__ ln3b,
              float* __restrict__ out)
{
    const int b = blockIdx.x;
    const int t = threadIdx.x;
    const int warp = t >> 5;
    const int lane = t & 31;

    const float* g1 = g_scratch + (size_t)b * FH;
    const float* g2 = g_scratch + (size_t)BB * FH + (size_t)b * FH;

    __shared__ float sm[16 * 4];

    float v1[8], v2[8];
    float s0 = 0.f, s1 = 0.f, s2 = 0.f, s3 = 0.f;
#pragma unroll
    for (int k = 0; k < 8; k++) {
        int j = t + k * 512;
        float a = g1[j], c = g2[j];
        v1[k] = a; v2[k] = c;
        s0 += a; s1 += a * a;
        s2 += c; s3 += c * c;
    }
#pragma unroll
    for (int o = 16; o > 0; o >>= 1) {
        s0 += __shfl_xor_sync(0xffffffffu, s0, o);
        s1 += __shfl_xor_sync(0xffffffffu, s1, o);
        s2 += __shfl_xor_sync(0xffffffffu, s2, o);
        s3 += __shfl_xor_sync(0xffffffffu, s3, o);
    }
    if (lane == 0) {
        sm[warp * 4 + 0] = s0; sm[warp * 4 + 1] = s1;
        sm[warp * 4 + 2] = s2; sm[warp * 4 + 3] = s3;
    }
    __syncthreads();
    float t0 = 0.f, t1 = 0.f, t2 = 0.f, t3 = 0.f;
#pragma unroll
    for (int w = 0; w < 16; w++) {
        t0 += sm[w * 4 + 0]; t1 += sm[w * 4 + 1];
        t2 += sm[w * 4 + 2]; t3 += sm[w * 4 + 3];
    }
    const float inv4h = 1.f / (float)FH;
    float mu1 = t0 * inv4h;
    float rs1 = rsqrtf(t1 * inv4h - mu1 * mu1 + EPSL);
    float mu2 = t2 * inv4h;
    float rs2 = rsqrtf(t3 * inv4h - mu2 * mu2 + EPSL);

    float c1v[2], ogv[2];
    float u0 = 0.f, u1 = 0.f;
#pragma unroll
    for (int p = 0; p < 2; p++) {
        int i = t + p * 512;
        int jf = i, ji = i + HH, jo = i + 2 * HH, jc = i + 3 * HH;
        float nf = (v1[p + 0] - mu1) * rs1 * ln1g[jf] + ln1b[jf]
                 + (v2[p + 0] - mu2) * rs2 * ln2g[jf] + ln2b[jf] + bias[jf];
        float ni = (v1[p + 2] - mu1) * rs1 * ln1g[ji] + ln1b[ji]
                 + (v2[p + 2] - mu2) * rs2 * ln2g[ji] + ln2b[ji] + bias[ji];
        float no = (v1[p + 4] - mu1) * rs1 * ln1g[jo] + ln1b[jo]
                 + (v2[p + 4] - mu2) * rs2 * ln2g[jo] + ln2b[jo] + bias[jo];
        float nc = (v1[p + 6] - mu1) * rs1 * ln1g[jc] + ln1b[jc]
                 + (v2[p + 6] - mu2) * rs2 * ln2g[jc] + ln2b[jc] + bias[jc];
        float c1 = sigf(nf) * c0[(size_t)b * HH + i] + sigf(ni) * tanhf(nc);
        c1v[p] = c1;
        ogv[p] = no;
        u0 += c1; u1 += c1 * c1;
    }

    __syncthreads();
#pragma unroll
    for (int o = 16; o > 0; o >>= 1) {
        u0 += __shfl_xor_sync(0xffffffffu, u0, o);
        u1 += __shfl_xor_sync(0xffffffffu, u1, o);
    }
    if (lane == 0) { sm[warp * 2 + 0] = u0; sm[warp * 2 + 1] = u1; }
    __syncthreads();
    float w0 = 0.f, w1 = 0.f;
#pragma unroll
    for (int w = 0; w < 16; w++) { w0 += sm[w * 2 + 0]; w1 += sm[w * 2 + 1]; }
    const float invh = 1.f / (float)HH;
    float mu3 = w0 * invh;
    float rs3 = rsqrtf(w1 * invh - mu3 * mu3 + EPSL);

#pragma unroll
    for (int p = 0; p < 2; p++) {
        int i = t + p * 512;
        float hn = (c1v[p] - mu3) * rs3 * ln3g[i] + ln3b[i];
        float h1 = sigf(ogv[p]) * tanhf(hn);
        out[(size_t)b * HH + i] = h1;
        out[(size_t)BB * HH + (size_t)b * HH + i] = c1v[p];
    }
}

// ---------------------------------------------------------------------------
// Launch
// ---------------------------------------------------------------------------
extern "C" void kernel_launch(void* const* d_in, const int* in_sizes, int n_in,
                              void* d_out, int out_size)
{
    const float* x    = (const float*)d_in[0];
    const float* h0   = (const float*)d_in[1];
    const float* c0   = (const float*)d_in[2];
    const float* Wh   = (const float*)d_in[3];
    const float* Wx   = (const float*)d_in[4];
    const float* bias = (const float*)d_in[5];
    const float* ln1g = (const float*)d_in[6];
    const float* ln1b = (const float*)d_in[7];
    const float* ln2g = (const float*)d_in[8];
    const float* ln2b = (const float*)d_in[9];
    const float* ln3g = (const float*)d_in[10];
    const float* ln3b = (const float*)d_in[11];
    float* out = (float*)d_out;

    static bool attr_set = false;
    if (!attr_set) {
        cudaFuncSetAttribute(hmma_gemm,
                             cudaFuncAttributeMaxDynamicSharedMemorySize,
                             GEMM_SMEM);
        attr_set = true;
    }

    conv_act<<<BB * KK / 1024, 256>>>(h0, 0);
    conv_act<<<BB * KK / 1024, 256>>>(x, 1);
    conv_w<<<dim3(FH / 32, KK / 32), 256>>>(Wh, 0);
    conv_w<<<dim3(FH / 32, KK / 32), 256>>>(Wx, 1);

    dim3 ggrid(FH / BN, BB / BM, 2);   // (16, 64, 2): both GEMMs in one launch
    hmma_gemm<<<ggrid, 256, GEMM_SMEM>>>();

    lstm_epilogue<<<BB, 512>>>(c0, bias, ln1g, ln1b, ln2g, ln2b, ln3g, ln3b, out);
}

// round 6
// speedup vs baseline: 4.7406x; 2.3509x over previous
#include <cuda_runtime.h>
#include <cuda_bf16.h>
#include <cuda_fp16.h>
#include <math.h>
#include <cstdint>

// Problem shape (fixed): B=8192, D=H=1024, 4H=4096
#define BB   8192
#define HH   1024
#define FH   4096
#define KK   1024
#define EPSL 1e-5f

// ---------------------------------------------------------------------------
// Static device scratch
// g_ah : fp16 activations (h0, x), [BB, 1024], row stride 2048 B
// g_wh : fp16 W^T * 32   (Wh, Wx), [FH, 1024], row stride 2048 B
// GEMM accumulator rescaled by 1/32 at store.
// ---------------------------------------------------------------------------
__device__ float g_scratch[2ULL * BB * FH];
__device__ __half g_ah[2][(size_t)BB * KK];
__device__ __half g_wh[2][(size_t)FH * KK];

// ---------------------------------------------------------------------------
// helpers
// ---------------------------------------------------------------------------
__device__ __forceinline__ uint32_t smem_u32(const void* p) {
    uint32_t a;
    asm("{ .reg .u64 t; cvta.to.shared.u64 t, %1; cvt.u32.u64 %0, t; }"
        : "=r"(a) : "l"(p));
    return a;
}

__device__ __forceinline__ void ldmx4(uint32_t* r, uint32_t addr) {
    asm volatile("ldmatrix.sync.aligned.m8n8.x4.shared.b16 {%0,%1,%2,%3}, [%4];"
                 : "=r"(r[0]), "=r"(r[1]), "=r"(r[2]), "=r"(r[3]) : "r"(addr));
}

__device__ __forceinline__ void mma_f16(float* d, const uint32_t* a,
                                        const uint32_t* b) {
    asm volatile(
        "mma.sync.aligned.m16n8k16.row.col.f32.f16.f16.f32 "
        "{%0,%1,%2,%3}, {%4,%5,%6,%7}, {%8,%9}, {%0,%1,%2,%3};"
        : "+f"(d[0]), "+f"(d[1]), "+f"(d[2]), "+f"(d[3])
        : "r"(a[0]), "r"(a[1]), "r"(a[2]), "r"(a[3]), "r"(b[0]), "r"(b[1]));
}

// ---------------------------------------------------------------------------
// Conversions
// ---------------------------------------------------------------------------
__global__ void __launch_bounds__(256)
conv_act(const float* __restrict__ in, int which)
{
    size_t i = (size_t)blockIdx.x * 256 + threadIdx.x;   // float4 index
    float4 v = reinterpret_cast<const float4*>(in)[i];
    __half2 p0 = __floats2half2_rn(v.x, v.y);
    __half2 p1 = __floats2half2_rn(v.z, v.w);
    __half2* dst = reinterpret_cast<__half2*>(g_ah[which]);
    dst[2 * i + 0] = p0;
    dst[2 * i + 1] = p1;
}

// W [KK, FH] fp32 -> W^T [FH, KK] fp16 scaled by 32
__global__ void __launch_bounds__(256)
conv_w(const float* __restrict__ W, int which)
{
    __shared__ float ts[32][33];
    int n0 = blockIdx.x * 32, k0 = blockIdx.y * 32;
    int tx = threadIdx.x & 31, ty = threadIdx.x >> 5;   // ty 0..7
#pragma unroll
    for (int d = 0; d < 32; d += 8)
        ts[ty + d][tx] = W[(size_t)(k0 + ty + d) * FH + n0 + tx];
    __syncthreads();
#pragma unroll
    for (int d = 0; d < 4; d++) {
        int nl = ty + d * 8;
        float v = ts[tx][nl];
        g_wh[which][(size_t)(n0 + nl) * KK + k0 + tx] =
            __float2half_rn(32.0f * v);
    }
}

// ---------------------------------------------------------------------------
// GEMM: C[M,N] = (Ah @ (32*W)^T) * (1/32)
// CTA tile 128x256, 256 threads, 64 k-bytes (32 fp16) per iter, 3-stage
// cp.async pipeline, 32 iterations. Smem rows padded to 80B.
// ---------------------------------------------------------------------------
#define BM 128
#define BN 256
#define ROWB 80u
#define AS_BYTES (BM * ROWB)
#define BS_BYTES (BN * ROWB)
#define STG_BYTES (AS_BYTES + BS_BYTES)    // 30720
#define NSTAGE 3
#define GEMM_SMEM (NSTAGE * STG_BYTES)     // 92160
#define GROWB 2048                          // global row stride (bytes)
#define ITERS 32

__device__ __forceinline__ void load_stage(const char* __restrict__ Ab,
                                           const char* __restrict__ Bb,
                                           int kbyte, uint32_t stage_base, int tid)
{
#pragma unroll
    for (int j = 0; j < 2; j++) {
        int idx = tid + j * 256;
        int r = idx >> 2, c = idx & 3;
        const void* g = Ab + (size_t)r * GROWB + kbyte + c * 16;
        uint32_t sa = stage_base + (uint32_t)r * ROWB + (uint32_t)c * 16;
        asm volatile("cp.async.cg.shared.global [%0], [%1], 16;" :: "r"(sa), "l"(g));
    }
    uint32_t bs = stage_base + AS_BYTES;
#pragma unroll
    for (int j = 0; j < 4; j++) {
        int idx = tid + j * 256;
        int r = idx >> 2, c = idx & 3;
        const void* g = Bb + (size_t)r * GROWB + kbyte + c * 16;
        uint32_t sa = bs + (uint32_t)r * ROWB + (uint32_t)c * 16;
        asm volatile("cp.async.cg.shared.global [%0], [%1], 16;" :: "r"(sa), "l"(g));
    }
}

__global__ void __launch_bounds__(256, 1)
hmma_gemm()
{
    extern __shared__ char smem[];
    const uint32_t sb = smem_u32(smem);
    const int tid  = threadIdx.x;
    const int wid  = tid >> 5;
    const int lane = tid & 31;
    const int wm   = wid >> 2;            // 0..1
    const int wn   = wid & 3;             // 0..3
    const int n0   = blockIdx.x * BN;
    const int m0   = blockIdx.y * BM;
    const int which = blockIdx.z;

    const char* Ah = (const char*)g_ah[which] + (size_t)m0 * GROWB;
    const char* Bh = (const char*)g_wh[which] + (size_t)n0 * GROWB;
    float* C = g_scratch + (size_t)which * BB * FH;

    // per-lane ldmatrix byte offsets (relative to stage base); kh adds 32
    const int quad = lane >> 3, lrow = lane & 7;
    uint32_t a_off[4], b_off[4];
#pragma unroll
    for (int mi = 0; mi < 4; mi++) {
        int row = wm * 64 + mi * 16 + (quad & 1) * 8 + lrow;
        a_off[mi] = (uint32_t)row * ROWB + (uint32_t)(quad >> 1) * 16;
    }
#pragma unroll
    for (int np = 0; np < 4; np++) {
        int row = wn * 64 + np * 16 + (quad >> 1) * 8 + lrow;
        b_off[np] = AS_BYTES + (uint32_t)row * ROWB + (uint32_t)(quad & 1) * 16;
    }

    float d[4][8][4];
#pragma unroll
    for (int mi = 0; mi < 4; mi++)
#pragma unroll
        for (int nt = 0; nt < 8; nt++)
#pragma unroll
            for (int q = 0; q < 4; q++) d[mi][nt][q] = 0.f;

    // prologue: stages 0 and 1
    load_stage(Ah, Bh, 0, sb, tid);
    asm volatile("cp.async.commit_group;");
    load_stage(Ah, Bh, 64, sb + STG_BYTES, tid);
    asm volatile("cp.async.commit_group;");

#pragma unroll 1
    for (int it = 0; it < ITERS; it++) {
        asm volatile("cp.async.wait_group %0;" :: "n"(1) : "memory");
        __syncthreads();

        int li = it + 2;
        if (li < ITERS)
            load_stage(Ah, Bh, li * 64,
                       sb + (uint32_t)(li % NSTAGE) * STG_BYTES, tid);
        asm volatile("cp.async.commit_group;");

        const uint32_t st = sb + (uint32_t)(it % NSTAGE) * STG_BYTES;
#pragma unroll
        for (int kh = 0; kh < 2; kh++) {
            uint32_t a[4][4], b[4][4];
#pragma unroll
            for (int mi = 0; mi < 4; mi++)
                ldmx4(a[mi], st + a_off[mi] + kh * 32);
#pragma unroll
            for (int np = 0; np < 4; np++)
                ldmx4(b[np], st + b_off[np] + kh * 32);
#pragma unroll
            for (int mi = 0; mi < 4; mi++)
#pragma unroll
                for (int np = 0; np < 4; np++) {
                    mma_f16(d[mi][np * 2 + 0], a[mi], &b[np][0]);
                    mma_f16(d[mi][np * 2 + 1], a[mi], &b[np][2]);
                }
        }
    }

    // epilogue: rescale by 1/32 (weights pre-scaled x32), float2 stores
    const float s = 0.03125f;
    const int r_base = m0 + wm * 64 + (lane >> 2);
    const int c_base = n0 + wn * 64 + (lane & 3) * 2;
#pragma unroll
    for (int mi = 0; mi < 4; mi++) {
#pragma unroll
        for (int nt = 0; nt < 8; nt++) {
            int rr = r_base + mi * 16;
            int cc = c_base + nt * 8;
            *reinterpret_cast<float2*>(C + (size_t)rr * FH + cc) =
                make_float2(d[mi][nt][0] * s, d[mi][nt][1] * s);
            *reinterpret_cast<float2*>(C + (size_t)(rr + 8) * FH + cc) =
                make_float2(d[mi][nt][2] * s, d[mi][nt][3] * s);
        }
    }
}

// ---------------------------------------------------------------------------
// Fused LSTM epilogue (unchanged)
// ---------------------------------------------------------------------------
__device__ __forceinline__ float sigf(float x) { return 1.f / (1.f + expf(-x)); }

__global__ void __launch_bounds__(512)
lstm_epilogue(const float* __restrict__ c0,   const float* __restrict__ bias,
              const float* __restrict__ ln1g, const float* __restrict__ ln1b,
              const float* __restrict__ ln2g, const float* __restrict__ ln2b,
              const float* __restrict__ ln3g, const float* __restrict__ ln3b,
              float* __restrict__ out)
{
    const int b = blockIdx.x;
    const int t = threadIdx.x;
    const int warp = t >> 5;
    const int lane = t & 31;

    const float* g1 = g_scratch + (size_t)b * FH;
    const float* g2 = g_scratch + (size_t)BB * FH + (size_t)b * FH;

    __shared__ float sm[16 * 4];

    float v1[8], v2[8];
    float s0 = 0.f, s1 = 0.f, s2 = 0.f, s3 = 0.f;
#pragma unroll
    for (int k = 0; k < 8; k++) {
        int j = t + k * 512;
        float a = g1[j], c = g2[j];
        v1[k] = a; v2[k] = c;
        s0 += a; s1 += a * a;
        s2 += c; s3 += c * c;
    }
#pragma unroll
    for (int o = 16; o > 0; o >>= 1) {
        s0 += __shfl_xor_sync(0xffffffffu, s0, o);
        s1 += __shfl_xor_sync(0xffffffffu, s1, o);
        s2 += __shfl_xor_sync(0xffffffffu, s2, o);
        s3 += __shfl_xor_sync(0xffffffffu, s3, o);
    }
    if (lane == 0) {
        sm[warp * 4 + 0] = s0; sm[warp * 4 + 1] = s1;
        sm[warp * 4 + 2] = s2; sm[warp * 4 + 3] = s3;
    }
    __syncthreads();
    float t0 = 0.f, t1 = 0.f, t2 = 0.f, t3 = 0.f;
#pragma unroll
    for (int w = 0; w < 16; w++) {
        t0 += sm[w * 4 + 0]; t1 += sm[w * 4 + 1];
        t2 += sm[w * 4 + 2]; t3 += sm[w * 4 + 3];
    }
    const float inv4h = 1.f / (float)FH;
    float mu1 = t0 * inv4h;
    float rs1 = rsqrtf(t1 * inv4h - mu1 * mu1 + EPSL);
    float mu2 = t2 * inv4h;
    float rs2 = rsqrtf(t3 * inv4h - mu2 * mu2 + EPSL);

    float c1v[2], ogv[2];
    float u0 = 0.f, u1 = 0.f;
#pragma unroll
    for (int p = 0; p < 2; p++) {
        int i = t + p * 512;
        int jf = i, ji = i + HH, jo = i + 2 * HH, jc = i + 3 * HH;
        float nf = (v1[p + 0] - mu1) * rs1 * ln1g[jf] + ln1b[jf]
                 + (v2[p + 0] - mu2) * rs2 * ln2g[jf] + ln2b[jf] + bias[jf];
        float ni = (v1[p + 2] - mu1) * rs1 * ln1g[ji] + ln1b[ji]
                 + (v2[p + 2] - mu2) * rs2 * ln2g[ji] + ln2b[ji] + bias[ji];
        float no = (v1[p + 4] - mu1) * rs1 * ln1g[jo] + ln1b[jo]
                 + (v2[p + 4] - mu2) * rs2 * ln2g[jo] + ln2b[jo] + bias[jo];
        float nc = (v1[p + 6] - mu1) * rs1 * ln1g[jc] + ln1b[jc]
                 + (v2[p + 6] - mu2) * rs2 * ln2g[jc] + ln2b[jc] + bias[jc];
        float c1 = sigf(nf) * c0[(size_t)b * HH + i] + sigf(ni) * tanhf(nc);
        c1v[p] = c1;
        ogv[p] = no;
        u0 += c1; u1 += c1 * c1;
    }

    __syncthreads();
#pragma unroll
    for (int o = 16; o > 0; o >>= 1) {
        u0 += __shfl_xor_sync(0xffffffffu, u0, o);
        u1 += __shfl_xor_sync(0xffffffffu, u1, o);
    }
    if (lane == 0) { sm[warp * 2 + 0] = u0; sm[warp * 2 + 1] = u1; }
    __syncthreads();
    float w0 = 0.f, w1 = 0.f;
#pragma unroll
    for (int w = 0; w < 16; w++) { w0 += sm[w * 2 + 0]; w1 += sm[w * 2 + 1]; }
    const float invh = 1.f / (float)HH;
    float mu3 = w0 * invh;
    float rs3 = rsqrtf(w1 * invh - mu3 * mu3 + EPSL);

#pragma unroll
    for (int p = 0; p < 2; p++) {
        int i = t + p * 512;
        float hn = (c1v[p] - mu3) * rs3 * ln3g[i] + ln3b[i];
        float h1 = sigf(ogv[p]) * tanhf(hn);
        out[(size_t)b * HH + i] = h1;
        out[(size_t)BB * HH + (size_t)b * HH + i] = c1v[p];
    }
}

// ---------------------------------------------------------------------------
// Launch
// ---------------------------------------------------------------------------
extern "C" void kernel_launch(void* const* d_in, const int* in_sizes, int n_in,
                              void* d_out, int out_size)
{
    const float* x    = (const float*)d_in[0];
    const float* h0   = (const float*)d_in[1];
    const float* c0   = (const float*)d_in[2];
    const float* Wh   = (const float*)d_in[3];
    const float* Wx   = (const float*)d_in[4];
    const float* bias = (const float*)d_in[5];
    const float* ln1g = (const float*)d_in[6];
    const float* ln1b = (const float*)d_in[7];
    const float* ln2g = (const float*)d_in[8];
    const float* ln2b = (const float*)d_in[9];
    const float* ln3g = (const float*)d_in[10];
    const float* ln3b = (const float*)d_in[11];
    float* out = (float*)d_out;

    static bool attr_set = false;
    if (!attr_set) {
        cudaFuncSetAttribute(hmma_gemm,
                             cudaFuncAttributeMaxDynamicSharedMemorySize,
                             GEMM_SMEM);
        attr_set = true;
    }

    conv_act<<<BB * KK / 1024, 256>>>(h0, 0);
    conv_act<<<BB * KK / 1024, 256>>>(x, 1);
    conv_w<<<dim3(FH / 32, KK / 32), 256>>>(Wh, 0);
    conv_w<<<dim3(FH / 32, KK / 32), 256>>>(Wx, 1);

    dim3 ggrid(FH / BN, BB / BM, 2);   // (16, 64, 2): both GEMMs in one launch
    hmma_gemm<<<ggrid, 256, GEMM_SMEM>>>();

    lstm_epilogue<<<BB, 512>>>(c0, bias, ln1g, ln1b, ln2g, ln2b, ln3g, ln3b, out);
}

// round 7
// speedup vs baseline: 4.8321x; 1.0193x over previous
#include <cuda_runtime.h>
#include <cuda_bf16.h>
#include <cuda_fp16.h>
#include <math.h>
#include <cstdint>

// Problem shape (fixed): B=8192, D=H=1024, 4H=4096
#define BB   8192
#define HH   1024
#define FH   4096
#define KK   1024
#define EPSL 1e-5f

// ---------------------------------------------------------------------------
// Static device scratch
// g_g16 : fp16 gate pre-activations (g1, g2), [BB, 4096]
// g_ah  : fp16 activations (h0, x), [BB, 1024]
// g_wh  : fp16 W^T * 32   (Wh, Wx), [FH, 1024]
// ---------------------------------------------------------------------------
__device__ __half g_g16[2][(size_t)BB * FH];
__device__ __half g_ah[2][(size_t)BB * KK];
__device__ __half g_wh[2][(size_t)FH * KK];

// ---------------------------------------------------------------------------
// helpers
// ---------------------------------------------------------------------------
__device__ __forceinline__ uint32_t smem_u32(const void* p) {
    uint32_t a;
    asm("{ .reg .u64 t; cvta.to.shared.u64 t, %1; cvt.u32.u64 %0, t; }"
        : "=r"(a) : "l"(p));
    return a;
}

__device__ __forceinline__ void ldmx4(uint32_t* r, uint32_t addr) {
    asm volatile("ldmatrix.sync.aligned.m8n8.x4.shared.b16 {%0,%1,%2,%3}, [%4];"
                 : "=r"(r[0]), "=r"(r[1]), "=r"(r[2]), "=r"(r[3]) : "r"(addr));
}

__device__ __forceinline__ void mma_f16(float* d, const uint32_t* a,
                                        const uint32_t* b) {
    asm volatile(
        "mma.sync.aligned.m16n8k16.row.col.f32.f16.f16.f32 "
        "{%0,%1,%2,%3}, {%4,%5,%6,%7}, {%8,%9}, {%0,%1,%2,%3};"
        : "+f"(d[0]), "+f"(d[1]), "+f"(d[2]), "+f"(d[3])
        : "r"(a[0]), "r"(a[1]), "r"(a[2]), "r"(a[3]), "r"(b[0]), "r"(b[1]));
}

// ---------------------------------------------------------------------------
// Conversions (merged: blockIdx.z selects which matrix)
// ---------------------------------------------------------------------------
__global__ void __launch_bounds__(256)
conv_act(const float* __restrict__ in0, const float* __restrict__ in1)
{
    const int which = blockIdx.z;
    const float* in = which ? in1 : in0;
    size_t i = (size_t)blockIdx.x * 256 + threadIdx.x;   // float4 index
    float4 v = reinterpret_cast<const float4*>(in)[i];
    __half2 p0 = __floats2half2_rn(v.x, v.y);
    __half2 p1 = __floats2half2_rn(v.z, v.w);
    __half2* dst = reinterpret_cast<__half2*>(g_ah[which]);
    dst[2 * i + 0] = p0;
    dst[2 * i + 1] = p1;
}

// W [KK, FH] fp32 -> W^T [FH, KK] fp16 scaled by 32
__global__ void __launch_bounds__(256)
conv_w(const float* __restrict__ W0, const float* __restrict__ W1)
{
    const int which = blockIdx.z;
    const float* W = which ? W1 : W0;
    __shared__ float ts[32][33];
    int n0 = blockIdx.x * 32, k0 = blockIdx.y * 32;
    int tx = threadIdx.x & 31, ty = threadIdx.x >> 5;   // ty 0..7
#pragma unroll
    for (int d = 0; d < 32; d += 8)
        ts[ty + d][tx] = W[(size_t)(k0 + ty + d) * FH + n0 + tx];
    __syncthreads();
#pragma unroll
    for (int d = 0; d < 4; d++) {
        int nl = ty + d * 8;
        float v = ts[tx][nl];
        g_wh[which][(size_t)(n0 + nl) * KK + k0 + tx] =
            __float2half_rn(32.0f * v);
    }
}

// ---------------------------------------------------------------------------
// GEMM: G16[M,N] = fp16( (Ah @ (32*W)^T) * (1/32) )
// CTA tile 128x256, 256 threads, 64 k-bytes (32 fp16) per iter, 3-stage
// cp.async pipeline, 32 iterations. Smem rows padded to 80B.
// ---------------------------------------------------------------------------
#define BM 128
#define BN 256
#define ROWB 80u
#define AS_BYTES (BM * ROWB)
#define BS_BYTES (BN * ROWB)
#define STG_BYTES (AS_BYTES + BS_BYTES)    // 30720
#define NSTAGE 3
#define GEMM_SMEM (NSTAGE * STG_BYTES)     // 92160
#define GROWB 2048                          // global row stride (bytes)
#define ITERS 32

__device__ __forceinline__ void load_stage(const char* __restrict__ Ab,
                                           const char* __restrict__ Bb,
                                           int kbyte, uint32_t stage_base, int tid)
{
#pragma unroll
    for (int j = 0; j < 2; j++) {
        int idx = tid + j * 256;
        int r = idx >> 2, c = idx & 3;
        const void* g = Ab + (size_t)r * GROWB + kbyte + c * 16;
        uint32_t sa = stage_base + (uint32_t)r * ROWB + (uint32_t)c * 16;
        asm volatile("cp.async.cg.shared.global [%0], [%1], 16;" :: "r"(sa), "l"(g));
    }
    uint32_t bs = stage_base + AS_BYTES;
#pragma unroll
    for (int j = 0; j < 4; j++) {
        int idx = tid + j * 256;
        int r = idx >> 2, c = idx & 3;
        const void* g = Bb + (size_t)r * GROWB + kbyte + c * 16;
        uint32_t sa = bs + (uint32_t)r * ROWB + (uint32_t)c * 16;
        asm volatile("cp.async.cg.shared.global [%0], [%1], 16;" :: "r"(sa), "l"(g));
    }
}

__global__ void __launch_bounds__(256, 1)
hmma_gemm()
{
    extern __shared__ char smem[];
    const uint32_t sb = smem_u32(smem);
    const int tid  = threadIdx.x;
    const int wid  = tid >> 5;
    const int lane = tid & 31;
    const int wm   = wid >> 2;            // 0..1
    const int wn   = wid & 3;             // 0..3
    const int n0   = blockIdx.x * BN;
    const int m0   = blockIdx.y * BM;
    const int which = blockIdx.z;

    const char* Ah = (const char*)g_ah[which] + (size_t)m0 * GROWB;
    const char* Bh = (const char*)g_wh[which] + (size_t)n0 * GROWB;
    __half* C = g_g16[which];

    // per-lane ldmatrix byte offsets (relative to stage base); kh adds 32
    const int quad = lane >> 3, lrow = lane & 7;
    uint32_t a_off[4], b_off[4];
#pragma unroll
    for (int mi = 0; mi < 4; mi++) {
        int row = wm * 64 + mi * 16 + (quad & 1) * 8 + lrow;
        a_off[mi] = (uint32_t)row * ROWB + (uint32_t)(quad >> 1) * 16;
    }
#pragma unroll
    for (int np = 0; np < 4; np++) {
        int row = wn * 64 + np * 16 + (quad >> 1) * 8 + lrow;
        b_off[np] = AS_BYTES + (uint32_t)row * ROWB + (uint32_t)(quad & 1) * 16;
    }

    float d[4][8][4];
#pragma unroll
    for (int mi = 0; mi < 4; mi++)
#pragma unroll
        for (int nt = 0; nt < 8; nt++)
#pragma unroll
            for (int q = 0; q < 4; q++) d[mi][nt][q] = 0.f;

    // prologue: stages 0 and 1
    load_stage(Ah, Bh, 0, sb, tid);
    asm volatile("cp.async.commit_group;");
    load_stage(Ah, Bh, 64, sb + STG_BYTES, tid);
    asm volatile("cp.async.commit_group;");

#pragma unroll 1
    for (int it = 0; it < ITERS; it++) {
        asm volatile("cp.async.wait_group %0;" :: "n"(1) : "memory");
        __syncthreads();

        int li = it + 2;
        if (li < ITERS)
            load_stage(Ah, Bh, li * 64,
                       sb + (uint32_t)(li % NSTAGE) * STG_BYTES, tid);
        asm volatile("cp.async.commit_group;");

        const uint32_t st = sb + (uint32_t)(it % NSTAGE) * STG_BYTES;
#pragma unroll
        for (int kh = 0; kh < 2; kh++) {
            uint32_t a[4][4], b[4][4];
#pragma unroll
            for (int mi = 0; mi < 4; mi++)
                ldmx4(a[mi], st + a_off[mi] + kh * 32);
#pragma unroll
            for (int np = 0; np < 4; np++)
                ldmx4(b[np], st + b_off[np] + kh * 32);
#pragma unroll
            for (int mi = 0; mi < 4; mi++)
#pragma unroll
                for (int np = 0; np < 4; np++) {
                    mma_f16(d[mi][np * 2 + 0], a[mi], &b[np][0]);
                    mma_f16(d[mi][np * 2 + 1], a[mi], &b[np][2]);
                }
        }
    }

    // epilogue: rescale by 1/32 (weights pre-scaled x32), store fp16 pairs
    const float s = 0.03125f;
    const int r_base = m0 + wm * 64 + (lane >> 2);
    const int c_base = n0 + wn * 64 + (lane & 3) * 2;
#pragma unroll
    for (int mi = 0; mi < 4; mi++) {
#pragma unroll
        for (int nt = 0; nt < 8; nt++) {
            int rr = r_base + mi * 16;
            int cc = c_base + nt * 8;
            *reinterpret_cast<__half2*>(C + (size_t)rr * FH + cc) =
                __floats2half2_rn(d[mi][nt][0] * s, d[mi][nt][1] * s);
            *reinterpret_cast<__half2*>(C + (size_t)(rr + 8) * FH + cc) =
                __floats2half2_rn(d[mi][nt][2] * s, d[mi][nt][3] * s);
        }
    }
}

// ---------------------------------------------------------------------------
// Fused LSTM epilogue (reads fp16 scratch)
// ---------------------------------------------------------------------------
__device__ __forceinline__ float sigf(float x) { return 1.f / (1.f + expf(-x)); }

__global__ void __launch_bounds__(512)
lstm_epilogue(const float* __restrict__ c0,   const float* __restrict__ bias,
              const float* __restrict__ ln1g, const float* __restrict__ ln1b,
              const float* __restrict__ ln2g, const float* __restrict__ ln2b,
              const float* __restrict__ ln3g, const float* __restrict__ ln3b,
              float* __restrict__ out)
{
    const int b = blockIdx.x;
    const int t = threadIdx.x;
    const int warp = t >> 5;
    const int lane = t & 31;

    const __half* g1 = g_g16[0] + (size_t)b * FH;
    const __half* g2 = g_g16[1] + (size_t)b * FH;

    __shared__ float sm[16 * 4];

    float v1[8], v2[8];
    float s0 = 0.f, s1 = 0.f, s2 = 0.f, s3 = 0.f;
#pragma unroll
    for (int k = 0; k < 8; k++) {
        int j = t + k * 512;
        float a = __half2float(g1[j]);
        float c = __half2float(g2[j]);
        v1[k] = a; v2[k] = c;
        s0 += a; s1 += a * a;
        s2 += c; s3 += c * c;
    }
#pragma unroll
    for (int o = 16; o > 0; o >>= 1) {
        s0 += __shfl_xor_sync(0xffffffffu, s0, o);
        s1 += __shfl_xor_sync(0xffffffffu, s1, o);
        s2 += __shfl_xor_sync(0xffffffffu, s2, o);
        s3 += __shfl_xor_sync(0xffffffffu, s3, o);
    }
    if (lane == 0) {
        sm[warp * 4 + 0] = s0; sm[warp * 4 + 1] = s1;
        sm[warp * 4 + 2] = s2; sm[warp * 4 + 3] = s3;
    }
    __syncthreads();
    float t0 = 0.f, t1 = 0.f, t2 = 0.f, t3 = 0.f;
#pragma unroll
    for (int w = 0; w < 16; w++) {
        t0 += sm[w * 4 + 0]; t1 += sm[w * 4 + 1];
        t2 += sm[w * 4 + 2]; t3 += sm[w * 4 + 3];
    }
    const float inv4h = 1.f / (float)FH;
    float mu1 = t0 * inv4h;
    float rs1 = rsqrtf(t1 * inv4h - mu1 * mu1 + EPSL);
    float mu2 = t2 * inv4h;
    float rs2 = rsqrtf(t3 * inv4h - mu2 * mu2 + EPSL);

    float c1v[2], ogv[2];
    float u0 = 0.f, u1 = 0.f;
#pragma unroll
    for (int p = 0; p < 2; p++) {
        int i = t + p * 512;
        int jf = i, ji = i + HH, jo = i + 2 * HH, jc = i + 3 * HH;
        float nf = (v1[p + 0] - mu1) * rs1 * ln1g[jf] + ln1b[jf]
                 + (v2[p + 0] - mu2) * rs2 * ln2g[jf] + ln2b[jf] + bias[jf];
        float ni = (v1[p + 2] - mu1) * rs1 * ln1g[ji] + ln1b[ji]
                 + (v2[p + 2] - mu2) * rs2 * ln2g[ji] + ln2b[ji] + bias[ji];
        float no = (v1[p + 4] - mu1) * rs1 * ln1g[jo] + ln1b[jo]
                 + (v2[p + 4] - mu2) * rs2 * ln2g[jo] + ln2b[jo] + bias[jo];
        float nc = (v1[p + 6] - mu1) * rs1 * ln1g[jc] + ln1b[jc]
                 + (v2[p + 6] - mu2) * rs2 * ln2g[jc] + ln2b[jc] + bias[jc];
        float c1 = sigf(nf) * c0[(size_t)b * HH + i] + sigf(ni) * tanhf(nc);
        c1v[p] = c1;
        ogv[p] = no;
        u0 += c1; u1 += c1 * c1;
    }

    __syncthreads();
#pragma unroll
    for (int o = 16; o > 0; o >>= 1) {
        u0 += __shfl_xor_sync(0xffffffffu, u0, o);
        u1 += __shfl_xor_sync(0xffffffffu, u1, o);
    }
    if (lane == 0) { sm[warp * 2 + 0] = u0; sm[warp * 2 + 1] = u1; }
    __syncthreads();
    float w0 = 0.f, w1 = 0.f;
#pragma unroll
    for (int w = 0; w < 16; w++) { w0 += sm[w * 2 + 0]; w1 += sm[w * 2 + 1]; }
    const float invh = 1.f / (float)HH;
    float mu3 = w0 * invh;
    float rs3 = rsqrtf(w1 * invh - mu3 * mu3 + EPSL);

#pragma unroll
    for (int p = 0; p < 2; p++) {
        int i = t + p * 512;
        float hn = (c1v[p] - mu3) * rs3 * ln3g[i] + ln3b[i];
        float h1 = sigf(ogv[p]) * tanhf(hn);
        out[(size_t)b * HH + i] = h1;
        out[(size_t)BB * HH + (size_t)b * HH + i] = c1v[p];
    }
}

// ---------------------------------------------------------------------------
// Launch
// ---------------------------------------------------------------------------
extern "C" void kernel_launch(void* const* d_in, const int* in_sizes, int n_in,
                              void* d_out, int out_size)
{
    const float* x    = (const float*)d_in[0];
    const float* h0   = (const float*)d_in[1];
    const float* c0   = (const float*)d_in[2];
    const float* Wh   = (const float*)d_in[3];
    const float* Wx   = (const float*)d_in[4];
    const float* bias = (const float*)d_in[5];
    const float* ln1g = (const float*)d_in[6];
    const float* ln1b = (const float*)d_in[7];
    const float* ln2g = (const float*)d_in[8];
    const float* ln2b = (const float*)d_in[9];
    const float* ln3g = (const float*)d_in[10];
    const float* ln3b = (const float*)d_in[11];
    float* out = (float*)d_out;

    static bool attr_set = false;
    if (!attr_set) {
        cudaFuncSetAttribute(hmma_gemm,
                             cudaFuncAttributeMaxDynamicSharedMemorySize,
                             GEMM_SMEM);
        attr_set = true;
    }

    conv_act<<<dim3(BB * KK / 1024, 1, 2), 256>>>(h0, x);
    conv_w<<<dim3(FH / 32, KK / 32, 2), 256>>>(Wh, Wx);

    dim3 ggrid(FH / BN, BB / BM, 2);   // (16, 64, 2): both GEMMs in one launch
    hmma_gemm<<<ggrid, 256, GEMM_SMEM>>>();

    lstm_epilogue<<<BB, 512>>>(c0, bias, ln1g, ln1b, ln2g, ln2b, ln3g, ln3b, out);
}

// round 8
// speedup vs baseline: 5.2722x; 1.0911x over previous
#include <cuda_runtime.h>
#include <cuda_bf16.h>
#include <cuda_fp16.h>
#include <math.h>
#include <cstdint>

// Problem shape (fixed): B=8192, D=H=1024, 4H=4096
#define BB   8192
#define HH   1024
#define FH   4096
#define KK   1024
#define EPSL 1e-5f

// ---------------------------------------------------------------------------
// Static device scratch
// ---------------------------------------------------------------------------
__device__ __half g_g16[2][(size_t)BB * FH];
__device__ __half g_ah[2][(size_t)BB * KK];
__device__ __half g_wh[2][(size_t)FH * KK];

// ---------------------------------------------------------------------------
// helpers
// ---------------------------------------------------------------------------
__device__ __forceinline__ uint32_t smem_u32(const void* p) {
    uint32_t a;
    asm("{ .reg .u64 t; cvta.to.shared.u64 t, %1; cvt.u32.u64 %0, t; }"
        : "=r"(a) : "l"(p));
    return a;
}

__device__ __forceinline__ void ldmx4(uint32_t* r, uint32_t addr) {
    asm volatile("ldmatrix.sync.aligned.m8n8.x4.shared.b16 {%0,%1,%2,%3}, [%4];"
                 : "=r"(r[0]), "=r"(r[1]), "=r"(r[2]), "=r"(r[3]) : "r"(addr));
}

__device__ __forceinline__ void mma_f16(float* d, const uint32_t* a,
                                        const uint32_t* b) {
    asm volatile(
        "mma.sync.aligned.m16n8k16.row.col.f32.f16.f16.f32 "
        "{%0,%1,%2,%3}, {%4,%5,%6,%7}, {%8,%9}, {%0,%1,%2,%3};"
        : "+f"(d[0]), "+f"(d[1]), "+f"(d[2]), "+f"(d[3])
        : "r"(a[0]), "r"(a[1]), "r"(a[2]), "r"(a[3]), "r"(b[0]), "r"(b[1]));
}

// ---------------------------------------------------------------------------
// Conversions (merged: blockIdx.z selects which matrix)
// ---------------------------------------------------------------------------
__global__ void __launch_bounds__(256)
conv_act(const float* __restrict__ in0, const float* __restrict__ in1)
{
    const int which = blockIdx.z;
    const float* in = which ? in1 : in0;
    size_t i = (size_t)blockIdx.x * 256 + threadIdx.x;   // float4 index
    float4 v = reinterpret_cast<const float4*>(in)[i];
    __half2 p0 = __floats2half2_rn(v.x, v.y);
    __half2 p1 = __floats2half2_rn(v.z, v.w);
    __half2* dst = reinterpret_cast<__half2*>(g_ah[which]);
    dst[2 * i + 0] = p0;
    dst[2 * i + 1] = p1;
}

// W [KK, FH] fp32 -> W^T [FH, KK] fp16 scaled by 32
__global__ void __launch_bounds__(256)
conv_w(const float* __restrict__ W0, const float* __restrict__ W1)
{
    const int which = blockIdx.z;
    const float* W = which ? W1 : W0;
    __shared__ float ts[32][33];
    int n0 = blockIdx.x * 32, k0 = blockIdx.y * 32;
    int tx = threadIdx.x & 31, ty = threadIdx.x >> 5;   // ty 0..7
#pragma unroll
    for (int d = 0; d < 32; d += 8)
        ts[ty + d][tx] = W[(size_t)(k0 + ty + d) * FH + n0 + tx];
    __syncthreads();
#pragma unroll
    for (int d = 0; d < 4; d++) {
        int nl = ty + d * 8;
        float v = ts[tx][nl];
        g_wh[which][(size_t)(n0 + nl) * KK + k0 + tx] =
            __float2half_rn(32.0f * v);
    }
}

// ---------------------------------------------------------------------------
// GEMM: G16[M,N] = fp16( (Ah @ (32*W)^T) * (1/32) )   (unchanged — at floor)
// ---------------------------------------------------------------------------
#define BM 128
#define BN 256
#define ROWB 80u
#define AS_BYTES (BM * ROWB)
#define BS_BYTES (BN * ROWB)
#define STG_BYTES (AS_BYTES + BS_BYTES)    // 30720
#define NSTAGE 3
#define GEMM_SMEM (NSTAGE * STG_BYTES)     // 92160
#define GROWB 2048
#define ITERS 32

__device__ __forceinline__ void load_stage(const char* __restrict__ Ab,
                                           const char* __restrict__ Bb,
                                           int kbyte, uint32_t stage_base, int tid)
{
#pragma unroll
    for (int j = 0; j < 2; j++) {
        int idx = tid + j * 256;
        int r = idx >> 2, c = idx & 3;
        const void* g = Ab + (size_t)r * GROWB + kbyte + c * 16;
        uint32_t sa = stage_base + (uint32_t)r * ROWB + (uint32_t)c * 16;
        asm volatile("cp.async.cg.shared.global [%0], [%1], 16;" :: "r"(sa), "l"(g));
    }
    uint32_t bs = stage_base + AS_BYTES;
#pragma unroll
    for (int j = 0; j < 4; j++) {
        int idx = tid + j * 256;
        int r = idx >> 2, c = idx & 3;
        const void* g = Bb + (size_t)r * GROWB + kbyte + c * 16;
        uint32_t sa = bs + (uint32_t)r * ROWB + (uint32_t)c * 16;
        asm volatile("cp.async.cg.shared.global [%0], [%1], 16;" :: "r"(sa), "l"(g));
    }
}

__global__ void __launch_bounds__(256, 1)
hmma_gemm()
{
    extern __shared__ char smem[];
    const uint32_t sb = smem_u32(smem);
    const int tid  = threadIdx.x;
    const int wid  = tid >> 5;
    const int lane = tid & 31;
    const int wm   = wid >> 2;
    const int wn   = wid & 3;
    const int n0   = blockIdx.x * BN;
    const int m0   = blockIdx.y * BM;
    const int which = blockIdx.z;

    const char* Ah = (const char*)g_ah[which] + (size_t)m0 * GROWB;
    const char* Bh = (const char*)g_wh[which] + (size_t)n0 * GROWB;
    __half* C = g_g16[which];

    const int quad = lane >> 3, lrow = lane & 7;
    uint32_t a_off[4], b_off[4];
#pragma unroll
    for (int mi = 0; mi < 4; mi++) {
        int row = wm * 64 + mi * 16 + (quad & 1) * 8 + lrow;
        a_off[mi] = (uint32_t)row * ROWB + (uint32_t)(quad >> 1) * 16;
    }
#pragma unroll
    for (int np = 0; np < 4; np++) {
        int row = wn * 64 + np * 16 + (quad >> 1) * 8 + lrow;
        b_off[np] = AS_BYTES + (uint32_t)row * ROWB + (uint32_t)(quad & 1) * 16;
    }

    float d[4][8][4];
#pragma unroll
    for (int mi = 0; mi < 4; mi++)
#pragma unroll
        for (int nt = 0; nt < 8; nt++)
#pragma unroll
            for (int q = 0; q < 4; q++) d[mi][nt][q] = 0.f;

    load_stage(Ah, Bh, 0, sb, tid);
    asm volatile("cp.async.commit_group;");
    load_stage(Ah, Bh, 64, sb + STG_BYTES, tid);
    asm volatile("cp.async.commit_group;");

#pragma unroll 1
    for (int it = 0; it < ITERS; it++) {
        asm volatile("cp.async.wait_group %0;" :: "n"(1) : "memory");
        __syncthreads();

        int li = it + 2;
        if (li < ITERS)
            load_stage(Ah, Bh, li * 64,
                       sb + (uint32_t)(li % NSTAGE) * STG_BYTES, tid);
        asm volatile("cp.async.commit_group;");

        const uint32_t st = sb + (uint32_t)(it % NSTAGE) * STG_BYTES;
#pragma unroll
        for (int kh = 0; kh < 2; kh++) {
            uint32_t a[4][4], b[4][4];
#pragma unroll
            for (int mi = 0; mi < 4; mi++)
                ldmx4(a[mi], st + a_off[mi] + kh * 32);
#pragma unroll
            for (int np = 0; np < 4; np++)
                ldmx4(b[np], st + b_off[np] + kh * 32);
#pragma unroll
            for (int mi = 0; mi < 4; mi++)
#pragma unroll
                for (int np = 0; np < 4; np++) {
                    mma_f16(d[mi][np * 2 + 0], a[mi], &b[np][0]);
                    mma_f16(d[mi][np * 2 + 1], a[mi], &b[np][2]);
                }
        }
    }

    const float s = 0.03125f;
    const int r_base = m0 + wm * 64 + (lane >> 2);
    const int c_base = n0 + wn * 64 + (lane & 3) * 2;
#pragma unroll
    for (int mi = 0; mi < 4; mi++) {
#pragma unroll
        for (int nt = 0; nt < 8; nt++) {
            int rr = r_base + mi * 16;
            int cc = c_base + nt * 8;
            *reinterpret_cast<__half2*>(C + (size_t)rr * FH + cc) =
                __floats2half2_rn(d[mi][nt][0] * s, d[mi][nt][1] * s);
            *reinterpret_cast<__half2*>(C + (size_t)(rr + 8) * FH + cc) =
                __floats2half2_rn(d[mi][nt][2] * s, d[mi][nt][3] * s);
        }
    }
}

// ---------------------------------------------------------------------------
// Fused LSTM epilogue: 256 threads x 4 consecutive hidden idx per thread.
// All gate loads are 8B vectors; all param loads are float4.
// ---------------------------------------------------------------------------
__device__ __forceinline__ float sigf(float x) { return 1.f / (1.f + expf(-x)); }

__global__ void __launch_bounds__(256)
lstm_epilogue(const float* __restrict__ c0,   const float* __restrict__ bias,
              const float* __restrict__ ln1g, const float* __restrict__ ln1b,
              const float* __restrict__ ln2g, const float* __restrict__ ln2b,
              const float* __restrict__ ln3g, const float* __restrict__ ln3b,
              float* __restrict__ out)
{
    const int b = blockIdx.x;
    const int t = threadIdx.x;          // 0..255
    const int warp = t >> 5;            // 0..7
    const int lane = t & 31;
    const int i0 = t * 4;               // first hidden index of this thread

    const __half* g1 = g_g16[0] + (size_t)b * FH;
    const __half* g2 = g_g16[1] + (size_t)b * FH;

    __shared__ float sm[8 * 4];

    // --- load gate pre-activations: quarter q, 4 consecutive fp16 each ---
    float v1[4][4], v2[4][4];
    float s0 = 0.f, s1 = 0.f, s2 = 0.f, s3 = 0.f;
#pragma unroll
    for (int q = 0; q < 4; q++) {
        uint2 u1 = *reinterpret_cast<const uint2*>(g1 + q * HH + i0);
        uint2 u2 = *reinterpret_cast<const uint2*>(g2 + q * HH + i0);
        float2 a01 = __half22float2(*reinterpret_cast<__half2*>(&u1.x));
        float2 a23 = __half22float2(*reinterpret_cast<__half2*>(&u1.y));
        float2 c01 = __half22float2(*reinterpret_cast<__half2*>(&u2.x));
        float2 c23 = __half22float2(*reinterpret_cast<__half2*>(&u2.y));
        v1[q][0] = a01.x; v1[q][1] = a01.y; v1[q][2] = a23.x; v1[q][3] = a23.y;
        v2[q][0] = c01.x; v2[q][1] = c01.y; v2[q][2] = c23.x; v2[q][3] = c23.y;
#pragma unroll
        for (int e = 0; e < 4; e++) {
            s0 += v1[q][e]; s1 += v1[q][e] * v1[q][e];
            s2 += v2[q][e]; s3 += v2[q][e] * v2[q][e];
        }
    }
#pragma unroll
    for (int o = 16; o > 0; o >>= 1) {
        s0 += __shfl_xor_sync(0xffffffffu, s0, o);
        s1 += __shfl_xor_sync(0xffffffffu, s1, o);
        s2 += __shfl_xor_sync(0xffffffffu, s2, o);
        s3 += __shfl_xor_sync(0xffffffffu, s3, o);
    }
    if (lane == 0) {
        sm[warp * 4 + 0] = s0; sm[warp * 4 + 1] = s1;
        sm[warp * 4 + 2] = s2; sm[warp * 4 + 3] = s3;
    }
    __syncthreads();
    float t0 = 0.f, t1 = 0.f, t2 = 0.f, t3 = 0.f;
#pragma unroll
    for (int w = 0; w < 8; w++) {
        t0 += sm[w * 4 + 0]; t1 += sm[w * 4 + 1];
        t2 += sm[w * 4 + 2]; t3 += sm[w * 4 + 3];
    }
    const float inv4h = 1.f / (float)FH;
    float mu1 = t0 * inv4h;
    float rs1 = rsqrtf(t1 * inv4h - mu1 * mu1 + EPSL);
    float mu2 = t2 * inv4h;
    float rs2 = rsqrtf(t3 * inv4h - mu2 * mu2 + EPSL);

    // --- combined gates: LN1(v1) + LN2(v2) + bias, vectorized params ---
    float gate[4][4];
#pragma unroll
    for (int q = 0; q < 4; q++) {
        float4 G1 = *reinterpret_cast<const float4*>(ln1g + q * HH + i0);
        float4 B1 = *reinterpret_cast<const float4*>(ln1b + q * HH + i0);
        float4 G2 = *reinterpret_cast<const float4*>(ln2g + q * HH + i0);
        float4 B2 = *reinterpret_cast<const float4*>(ln2b + q * HH + i0);
        float4 BS = *reinterpret_cast<const float4*>(bias + q * HH + i0);
        const float* G1f = &G1.x; const float* B1f = &B1.x;
        const float* G2f = &G2.x; const float* B2f = &B2.x;
        const float* BSf = &BS.x;
#pragma unroll
        for (int e = 0; e < 4; e++)
            gate[q][e] = (v1[q][e] - mu1) * rs1 * G1f[e] + B1f[e]
                       + (v2[q][e] - mu2) * rs2 * G2f[e] + B2f[e] + BSf[e];
    }

    // --- LSTM cell update ---
    float4 C0 = *reinterpret_cast<const float4*>(c0 + (size_t)b * HH + i0);
    const float* C0f = &C0.x;
    float c1v[4], u0 = 0.f, u1 = 0.f;
#pragma unroll
    for (int e = 0; e < 4; e++) {
        float c1 = sigf(gate[0][e]) * C0f[e]
                 + sigf(gate[1][e]) * tanhf(gate[3][e]);
        c1v[e] = c1;
        u0 += c1; u1 += c1 * c1;
    }

    // --- LN3 reduction over 1024 c1 values ---
    __syncthreads();
#pragma unroll
    for (int o = 16; o > 0; o >>= 1) {
        u0 += __shfl_xor_sync(0xffffffffu, u0, o);
        u1 += __shfl_xor_sync(0xffffffffu, u1, o);
    }
    if (lane == 0) { sm[warp * 2 + 0] = u0; sm[warp * 2 + 1] = u1; }
    __syncthreads();
    float w0 = 0.f, w1 = 0.f;
#pragma unroll
    for (int w = 0; w < 8; w++) { w0 += sm[w * 2 + 0]; w1 += sm[w * 2 + 1]; }
    const float invh = 1.f / (float)HH;
    float mu3 = w0 * invh;
    float rs3 = rsqrtf(w1 * invh - mu3 * mu3 + EPSL);

    float4 G3 = *reinterpret_cast<const float4*>(ln3g + i0);
    float4 B3 = *reinterpret_cast<const float4*>(ln3b + i0);
    const float* G3f = &G3.x; const float* B3f = &B3.x;
    float4 ho, co;
    float* hof = &ho.x; float* cof = &co.x;
#pragma unroll
    for (int e = 0; e < 4; e++) {
        float hn = (c1v[e] - mu3) * rs3 * G3f[e] + B3f[e];
        hof[e] = sigf(gate[2][e]) * tanhf(hn);
        cof[e] = c1v[e];
    }
    *reinterpret_cast<float4*>(out + (size_t)b * HH + i0) = ho;
    *reinterpret_cast<float4*>(out + (size_t)BB * HH + (size_t)b * HH + i0) = co;
}

// ---------------------------------------------------------------------------
// Launch
// ---------------------------------------------------------------------------
extern "C" void kernel_launch(void* const* d_in, const int* in_sizes, int n_in,
                              void* d_out, int out_size)
{
    const float* x    = (const float*)d_in[0];
    const float* h0   = (const float*)d_in[1];
    const float* c0   = (const float*)d_in[2];
    const float* Wh   = (const float*)d_in[3];
    const float* Wx   = (const float*)d_in[4];
    const float* bias = (const float*)d_in[5];
    const float* ln1g = (const float*)d_in[6];
    const float* ln1b = (const float*)d_in[7];
    const float* ln2g = (const float*)d_in[8];
    const float* ln2b = (const float*)d_in[9];
    const float* ln3g = (const float*)d_in[10];
    const float* ln3b = (const float*)d_in[11];
    float* out = (float*)d_out;

    static bool attr_set = false;
    if (!attr_set) {
        cudaFuncSetAttribute(hmma_gemm,
                             cudaFuncAttributeMaxDynamicSharedMemorySize,
                             GEMM_SMEM);
        attr_set = true;
    }

    conv_act<<<dim3(BB * KK / 1024, 1, 2), 256>>>(h0, x);
    conv_w<<<dim3(FH / 32, KK / 32, 2), 256>>>(Wh, Wx);

    dim3 ggrid(FH / BN, BB / BM, 2);   // (16, 64, 2): both GEMMs in one launch
    hmma_gemm<<<ggrid, 256, GEMM_SMEM>>>();

    lstm_epilogue<<<BB, 256>>>(c0, bias, ln1g, ln1b, ln2g, ln2b, ln3g, ln3b, out);
}

// round 9
// speedup vs baseline: 5.3543x; 1.0156x over previous
#include <cuda_runtime.h>
#include <cuda_bf16.h>
#include <cuda_fp16.h>
#include <math.h>
#include <cstdint>

// Problem shape (fixed): B=8192, D=H=1024, 4H=4096
#define BB   8192
#define HH   1024
#define FH   4096
#define KK   1024
#define EPSL 1e-5f

// ---------------------------------------------------------------------------
// Static device scratch
// ---------------------------------------------------------------------------
__device__ __half g_g16[2][(size_t)BB * FH];
__device__ __half g_ah[2][(size_t)BB * KK];
__device__ __half g_wh[2][(size_t)FH * KK];

// ---------------------------------------------------------------------------
// helpers
// ---------------------------------------------------------------------------
__device__ __forceinline__ uint32_t smem_u32(const void* p) {
    uint32_t a;
    asm("{ .reg .u64 t; cvta.to.shared.u64 t, %1; cvt.u32.u64 %0, t; }"
        : "=r"(a) : "l"(p));
    return a;
}

__device__ __forceinline__ void ldmx4(uint32_t* r, uint32_t addr) {
    asm volatile("ldmatrix.sync.aligned.m8n8.x4.shared.b16 {%0,%1,%2,%3}, [%4];"
                 : "=r"(r[0]), "=r"(r[1]), "=r"(r[2]), "=r"(r[3]) : "r"(addr));
}

__device__ __forceinline__ void mma_f16(float* d, const uint32_t* a,
                                        const uint32_t* b) {
    asm volatile(
        "mma.sync.aligned.m16n8k16.row.col.f32.f16.f16.f32 "
        "{%0,%1,%2,%3}, {%4,%5,%6,%7}, {%8,%9}, {%0,%1,%2,%3};"
        : "+f"(d[0]), "+f"(d[1]), "+f"(d[2]), "+f"(d[3])
        : "r"(a[0]), "r"(a[1]), "r"(a[2]), "r"(a[3]), "r"(b[0]), "r"(b[1]));
}

// fast transcendentals (forced MUFU path, overflow-safe for |x| < 80)
__device__ __forceinline__ float fsig(float x) {
    return __fdividef(1.f, 1.f + __expf(-x));
}
__device__ __forceinline__ float ftanh(float x) {
    float ax = fabsf(x);
    float t  = __expf(-2.f * ax);
    float r  = __fdividef(1.f - t, 1.f + t);
    return copysignf(r, x);
}

// ---------------------------------------------------------------------------
// Merged conversion kernel.
// blocks [0, 16384): activations  (z = bid >> 13, 8192 blocks each)
// blocks [16384, 24576): weights  (z = (bid-16384) >> 12, 4096 blocks each)
// ---------------------------------------------------------------------------
__global__ void __launch_bounds__(256)
conv_all(const float* __restrict__ h0, const float* __restrict__ x,
         const float* __restrict__ Wh, const float* __restrict__ Wx)
{
    const int bid = blockIdx.x;
    if (bid < 16384) {
        const int which = bid >> 13;
        const float* in = which ? x : h0;
        size_t i = (size_t)(bid & 8191) * 256 + threadIdx.x;   // float4 index
        float4 v = reinterpret_cast<const float4*>(in)[i];
        __half2 p0 = __floats2half2_rn(v.x, v.y);
        __half2 p1 = __floats2half2_rn(v.z, v.w);
        __half2* dst = reinterpret_cast<__half2*>(g_ah[which]);
        dst[2 * i + 0] = p0;
        dst[2 * i + 1] = p1;
    } else {
        __shared__ float ts[32][33];
        int r = bid - 16384;
        const int which = r >> 12;
        r &= 4095;
        const float* W = which ? Wx : Wh;
        int n0 = (r & 127) * 32, k0 = (r >> 7) * 32;
        int tx = threadIdx.x & 31, ty = threadIdx.x >> 5;   // ty 0..7
#pragma unroll
        for (int d = 0; d < 32; d += 8)
            ts[ty + d][tx] = W[(size_t)(k0 + ty + d) * FH + n0 + tx];
        __syncthreads();
#pragma unroll
        for (int d = 0; d < 4; d++) {
            int nl = ty + d * 8;
            float v = ts[tx][nl];
            g_wh[which][(size_t)(n0 + nl) * KK + k0 + tx] =
                __float2half_rn(32.0f * v);
        }
    }
}

// ---------------------------------------------------------------------------
// GEMM: G16[M,N] = fp16( (Ah @ (32*W)^T) * (1/32) )   (unchanged — at HW floor)
// ---------------------------------------------------------------------------
#define BM 128
#define BN 256
#define ROWB 80u
#define AS_BYTES (BM * ROWB)
#define BS_BYTES (BN * ROWB)
#define STG_BYTES (AS_BYTES + BS_BYTES)    // 30720
#define NSTAGE 3
#define GEMM_SMEM (NSTAGE * STG_BYTES)     // 92160
#define GROWB 2048
#define ITERS 32

__device__ __forceinline__ void load_stage(const char* __restrict__ Ab,
                                           const char* __restrict__ Bb,
                                           int kbyte, uint32_t stage_base, int tid)
{
#pragma unroll
    for (int j = 0; j < 2; j++) {
        int idx = tid + j * 256;
        int r = idx >> 2, c = idx & 3;
        const void* g = Ab + (size_t)r * GROWB + kbyte + c * 16;
        uint32_t sa = stage_base + (uint32_t)r * ROWB + (uint32_t)c * 16;
        asm volatile("cp.async.cg.shared.global [%0], [%1], 16;" :: "r"(sa), "l"(g));
    }
    uint32_t bs = stage_base + AS_BYTES;
#pragma unroll
    for (int j = 0; j < 4; j++) {
        int idx = tid + j * 256;
        int r = idx >> 2, c = idx & 3;
        const void* g = Bb + (size_t)r * GROWB + kbyte + c * 16;
        uint32_t sa = bs + (uint32_t)r * ROWB + (uint32_t)c * 16;
        asm volatile("cp.async.cg.shared.global [%0], [%1], 16;" :: "r"(sa), "l"(g));
    }
}

__global__ void __launch_bounds__(256, 1)
hmma_gemm()
{
    extern __shared__ char smem[];
    const uint32_t sb = smem_u32(smem);
    const int tid  = threadIdx.x;
    const int wid  = tid >> 5;
    const int lane = tid & 31;
    const int wm   = wid >> 2;
    const int wn   = wid & 3;
    const int n0   = blockIdx.x * BN;
    const int m0   = blockIdx.y * BM;
    const int which = blockIdx.z;

    const char* Ah = (const char*)g_ah[which] + (size_t)m0 * GROWB;
    const char* Bh = (const char*)g_wh[which] + (size_t)n0 * GROWB;
    __half* C = g_g16[which];

    const int quad = lane >> 3, lrow = lane & 7;
    uint32_t a_off[4], b_off[4];
#pragma unroll
    for (int mi = 0; mi < 4; mi++) {
        int row = wm * 64 + mi * 16 + (quad & 1) * 8 + lrow;
        a_off[mi] = (uint32_t)row * ROWB + (uint32_t)(quad >> 1) * 16;
    }
#pragma unroll
    for (int np = 0; np < 4; np++) {
        int row = wn * 64 + np * 16 + (quad >> 1) * 8 + lrow;
        b_off[np] = AS_BYTES + (uint32_t)row * ROWB + (uint32_t)(quad & 1) * 16;
    }

    float d[4][8][4];
#pragma unroll
    for (int mi = 0; mi < 4; mi++)
#pragma unroll
        for (int nt = 0; nt < 8; nt++)
#pragma unroll
            for (int q = 0; q < 4; q++) d[mi][nt][q] = 0.f;

    load_stage(Ah, Bh, 0, sb, tid);
    asm volatile("cp.async.commit_group;");
    load_stage(Ah, Bh, 64, sb + STG_BYTES, tid);
    asm volatile("cp.async.commit_group;");

#pragma unroll 1
    for (int it = 0; it < ITERS; it++) {
        asm volatile("cp.async.wait_group %0;" :: "n"(1) : "memory");
        __syncthreads();

        int li = it + 2;
        if (li < ITERS)
            load_stage(Ah, Bh, li * 64,
                       sb + (uint32_t)(li % NSTAGE) * STG_BYTES, tid);
        asm volatile("cp.async.commit_group;");

        const uint32_t st = sb + (uint32_t)(it % NSTAGE) * STG_BYTES;
#pragma unroll
        for (int kh = 0; kh < 2; kh++) {
            uint32_t a[4][4], b[4][4];
#pragma unroll
            for (int mi = 0; mi < 4; mi++)
                ldmx4(a[mi], st + a_off[mi] + kh * 32);
#pragma unroll
            for (int np = 0; np < 4; np++)
                ldmx4(b[np], st + b_off[np] + kh * 32);
#pragma unroll
            for (int mi = 0; mi < 4; mi++)
#pragma unroll
                for (int np = 0; np < 4; np++) {
                    mma_f16(d[mi][np * 2 + 0], a[mi], &b[np][0]);
                    mma_f16(d[mi][np * 2 + 1], a[mi], &b[np][2]);
                }
        }
    }

    const float s = 0.03125f;
    const int r_base = m0 + wm * 64 + (lane >> 2);
    const int c_base = n0 + wn * 64 + (lane & 3) * 2;
#pragma unroll
    for (int mi = 0; mi < 4; mi++) {
#pragma unroll
        for (int nt = 0; nt < 8; nt++) {
            int rr = r_base + mi * 16;
            int cc = c_base + nt * 8;
            *reinterpret_cast<__half2*>(C + (size_t)rr * FH + cc) =
                __floats2half2_rn(d[mi][nt][0] * s, d[mi][nt][1] * s);
            *reinterpret_cast<__half2*>(C + (size_t)(rr + 8) * FH + cc) =
                __floats2half2_rn(d[mi][nt][2] * s, d[mi][nt][3] * s);
        }
    }
}

// ---------------------------------------------------------------------------
// Fused LSTM epilogue: 256 threads x 4 consecutive hidden idx per thread.
// Vectorized loads; MUFU-path transcendentals.
// ---------------------------------------------------------------------------
__global__ void __launch_bounds__(256)
lstm_epilogue(const float* __restrict__ c0,   const float* __restrict__ bias,
              const float* __restrict__ ln1g, const float* __restrict__ ln1b,
              const float* __restrict__ ln2g, const float* __restrict__ ln2b,
              const float* __restrict__ ln3g, const float* __restrict__ ln3b,
              float* __restrict__ out)
{
    const int b = blockIdx.x;
    const int t = threadIdx.x;          // 0..255
    const int warp = t >> 5;            // 0..7
    const int lane = t & 31;
    const int i0 = t * 4;               // first hidden index of this thread

    const __half* g1 = g_g16[0] + (size_t)b * FH;
    const __half* g2 = g_g16[1] + (size_t)b * FH;

    __shared__ float sm[8 * 4];

    // --- load gate pre-activations: quarter q, 4 consecutive fp16 each ---
    float v1[4][4], v2[4][4];
    float s0 = 0.f, s1 = 0.f, s2 = 0.f, s3 = 0.f;
#pragma unroll
    for (int q = 0; q < 4; q++) {
        uint2 u1 = *reinterpret_cast<const uint2*>(g1 + q * HH + i0);
        uint2 u2 = *reinterpret_cast<const uint2*>(g2 + q * HH + i0);
        float2 a01 = __half22float2(*reinterpret_cast<__half2*>(&u1.x));
        float2 a23 = __half22float2(*reinterpret_cast<__half2*>(&u1.y));
        float2 c01 = __half22float2(*reinterpret_cast<__half2*>(&u2.x));
        float2 c23 = __half22float2(*reinterpret_cast<__half2*>(&u2.y));
        v1[q][0] = a01.x; v1[q][1] = a01.y; v1[q][2] = a23.x; v1[q][3] = a23.y;
        v2[q][0] = c01.x; v2[q][1] = c01.y; v2[q][2] = c23.x; v2[q][3] = c23.y;
#pragma unroll
        for (int e = 0; e < 4; e++) {
            s0 += v1[q][e]; s1 += v1[q][e] * v1[q][e];
            s2 += v2[q][e]; s3 += v2[q][e] * v2[q][e];
        }
    }
#pragma unroll
    for (int o = 16; o > 0; o >>= 1) {
        s0 += __shfl_xor_sync(0xffffffffu, s0, o);
        s1 += __shfl_xor_sync(0xffffffffu, s1, o);
        s2 += __shfl_xor_sync(0xffffffffu, s2, o);
        s3 += __shfl_xor_sync(0xffffffffu, s3, o);
    }
    if (lane == 0) {
        sm[warp * 4 + 0] = s0; sm[warp * 4 + 1] = s1;
        sm[warp * 4 + 2] = s2; sm[warp * 4 + 3] = s3;
    }
    __syncthreads();
    float t0 = 0.f, t1 = 0.f, t2 = 0.f, t3 = 0.f;
#pragma unroll
    for (int w = 0; w < 8; w++) {
        t0 += sm[w * 4 + 0]; t1 += sm[w * 4 + 1];
        t2 += sm[w * 4 + 2]; t3 += sm[w * 4 + 3];
    }
    const float inv4h = 1.f / (float)FH;
    float mu1 = t0 * inv4h;
    float rs1 = rsqrtf(t1 * inv4h - mu1 * mu1 + EPSL);
    float mu2 = t2 * inv4h;
    float rs2 = rsqrtf(t3 * inv4h - mu2 * mu2 + EPSL);

    // --- combined gates: LN1(v1) + LN2(v2) + bias, vectorized params ---
    float gate[4][4];
#pragma unroll
    for (int q = 0; q < 4; q++) {
        float4 G1 = *reinterpret_cast<const float4*>(ln1g + q * HH + i0);
        float4 B1 = *reinterpret_cast<const float4*>(ln1b + q * HH + i0);
        float4 G2 = *reinterpret_cast<const float4*>(ln2g + q * HH + i0);
        float4 B2 = *reinterpret_cast<const float4*>(ln2b + q * HH + i0);
        float4 BS = *reinterpret_cast<const float4*>(bias + q * HH + i0);
        const float* G1f = &G1.x; const float* B1f = &B1.x;
        const float* G2f = &G2.x; const float* B2f = &B2.x;
        const float* BSf = &BS.x;
#pragma unroll
        for (int e = 0; e < 4; e++)
            gate[q][e] = (v1[q][e] - mu1) * rs1 * G1f[e] + B1f[e]
                       + (v2[q][e] - mu2) * rs2 * G2f[e] + B2f[e] + BSf[e];
    }

    // --- LSTM cell update ---
    float4 C0 = *reinterpret_cast<const float4*>(c0 + (size_t)b * HH + i0);
    const float* C0f = &C0.x;
    float c1v[4], u0 = 0.f, u1 = 0.f;
#pragma unroll
    for (int e = 0; e < 4; e++) {
        float c1 = fsig(gate[0][e]) * C0f[e]
                 + fsig(gate[1][e]) * ftanh(gate[3][e]);
        c1v[e] = c1;
        u0 += c1; u1 += c1 * c1;
    }

    // --- LN3 reduction over 1024 c1 values ---
    __syncthreads();
#pragma unroll
    for (int o = 16; o > 0; o >>= 1) {
        u0 += __shfl_xor_sync(0xffffffffu, u0, o);
        u1 += __shfl_xor_sync(0xffffffffu, u1, o);
    }
    if (lane == 0) { sm[warp * 2 + 0] = u0; sm[warp * 2 + 1] = u1; }
    __syncthreads();
    float w0 = 0.f, w1 = 0.f;
#pragma unroll
    for (int w = 0; w < 8; w++) { w0 += sm[w * 2 + 0]; w1 += sm[w * 2 + 1]; }
    const float invh = 1.f / (float)HH;
    float mu3 = w0 * invh;
    float rs3 = rsqrtf(w1 * invh - mu3 * mu3 + EPSL);

    float4 G3 = *reinterpret_cast<const float4*>(ln3g + i0);
    float4 B3 = *reinterpret_cast<const float4*>(ln3b + i0);
    const float* G3f = &G3.x; const float* B3f = &B3.x;
    float4 ho, co;
    float* hof = &ho.x; float* cof = &co.x;
#pragma unroll
    for (int e = 0; e < 4; e++) {
        float hn = (c1v[e] - mu3) * rs3 * G3f[e] + B3f[e];
        hof[e] = fsig(gate[2][e]) * ftanh(hn);
        cof[e] = c1v[e];
    }
    *reinterpret_cast<float4*>(out + (size_t)b * HH + i0) = ho;
    *reinterpret_cast<float4*>(out + (size_t)BB * HH + (size_t)b * HH + i0) = co;
}

// ---------------------------------------------------------------------------
// Launch
// ---------------------------------------------------------------------------
extern "C" void kernel_launch(void* const* d_in, const int* in_sizes, int n_in,
                              void* d_out, int out_size)
{
    const float* x    = (const float*)d_in[0];
    const float* h0   = (const float*)d_in[1];
    const float* c0   = (const float*)d_in[2];
    const float* Wh   = (const float*)d_in[3];
    const float* Wx   = (const float*)d_in[4];
    const float* bias = (const float*)d_in[5];
    const float* ln1g = (const float*)d_in[6];
    const float* ln1b = (const float*)d_in[7];
    const float* ln2g = (const float*)d_in[8];
    const float* ln2b = (const float*)d_in[9];
    const float* ln3g = (const float*)d_in[10];
    const float* ln3b = (const float*)d_in[11];
    float* out = (float*)d_out;

    static bool attr_set = false;
    if (!attr_set) {
        cudaFuncSetAttribute(hmma_gemm,
                             cudaFuncAttributeMaxDynamicSharedMemorySize,
                             GEMM_SMEM);
        attr_set = true;
    }

    conv_all<<<24576, 256>>>(h0, x, Wh, Wx);

    dim3 ggrid(FH / BN, BB / BM, 2);   // (16, 64, 2): both GEMMs in one launch
    hmma_gemm<<<ggrid, 256, GEMM_SMEM>>>();

    lstm_epilogue<<<BB, 256>>>(c0, bias, ln1g, ln1b, ln2g, ln2b, ln3g, ln3b, out);
}